// round 9
// baseline (speedup 1.0000x reference)
#include <cuda_runtime.h>
#include <cuda_bf16.h>
#include <cstdint>

// ---------------- problem constants ----------------
#define NNODES 50000
#define NEDGES 800000
#define NREL   8
#define HID    256
#define NBASES 30
#define KTOT   2304            // 8*256 relation cols + 256 self cols
#define MPAD   50176           // array padding; GEMM uses 391*128 = 50048 rows

// ---------------- device scratch (static, .bss zero-initialized) ----------------
__device__ int   g_deg8[NNODES * NREL];              // per-(node,rel) counts
__device__ float g_deginv[NNODES];
__device__ int   g_rowptr8[NNODES * NREL + 8];       // per-(node,rel) CSR offsets
__device__ int   g_cursor8[NNODES * NREL];
__device__ int   g_edges[NEDGES];                    // src only (sorted by node,rel)
__device__ __align__(256) __nv_bfloat16 g_Ahi[(size_t)MPAD * KTOT];  // pad rows stay 0
__device__ __align__(256) __nv_bfloat16 g_Alo[(size_t)MPAD * KTOT];
__device__ float g_W[KTOT * HID];                    // W[k][o] fp32 (serial on s1)
__device__ __align__(256) __nv_bfloat16 g_Bhi[2][HID * KTOT];  // per-layer W^T hi: [o][k]
__device__ __align__(256) __nv_bfloat16 g_Blo[2][HID * KTOT];  // per-layer W^T lo: [o][k]
__device__ float g_x1[(size_t)MPAD * HID];

// ================= helpers =================
__device__ __forceinline__ uint32_t smem_to_u32(const void* p) {
    uint32_t a;
    asm("{ .reg .u64 t; cvta.to.shared.u64 t, %1; cvt.u32.u64 %0, t; }" : "=r"(a) : "l"(p));
    return a;
}
#define SWZ128(off) ((off) ^ (((off) >> 3) & 0x70))

__device__ __forceinline__ void cp16(uint32_t dst, const void* src) {
    asm volatile("cp.async.cg.shared.global [%0], [%1], 16;" :: "r"(dst), "l"(src));
}
__device__ __forceinline__ void ldsm4(uint32_t& r0, uint32_t& r1, uint32_t& r2, uint32_t& r3,
                                      uint32_t addr) {
    asm volatile("ldmatrix.sync.aligned.m8n8.x4.shared.b16 {%0,%1,%2,%3}, [%4];"
                 : "=r"(r0), "=r"(r1), "=r"(r2), "=r"(r3) : "r"(addr));
}
__device__ __forceinline__ void mma16816(float* c, const uint32_t* a, const uint32_t* b) {
    asm volatile("mma.sync.aligned.m16n8k16.row.col.f32.bf16.bf16.f32 "
                 "{%0,%1,%2,%3}, {%4,%5,%6,%7}, {%8,%9}, {%0,%1,%2,%3};"
                 : "+f"(c[0]), "+f"(c[1]), "+f"(c[2]), "+f"(c[3])
                 : "r"(a[0]), "r"(a[1]), "r"(a[2]), "r"(a[3]), "r"(b[0]), "r"(b[1]));
}

// ---------------- setup kernels ----------------
__global__ void hist_kernel(const int* __restrict__ dst, const int* __restrict__ rel) {
    int e = blockIdx.x * blockDim.x + threadIdx.x;
    if (e < NEDGES) atomicAdd(&g_deg8[dst[e] * NREL + rel[e]], 1);
}

// single-block shuffle scan over node degrees; also emits per-(node,rel) offsets
__global__ void scan_kernel() {
    __shared__ int wsum[32];
    int tid = threadIdx.x;
    int lane = tid & 31;
    int wid = tid >> 5;
    int carry = 0;
    for (int base = 0; base < NNODES; base += 1024) {
        int i = base + tid;
        int d8[8];
        int v = 0;
        if (i < NNODES) {
            int4 p0 = *reinterpret_cast<const int4*>(&g_deg8[i * 8]);
            int4 p1 = *reinterpret_cast<const int4*>(&g_deg8[i * 8 + 4]);
            d8[0] = p0.x; d8[1] = p0.y; d8[2] = p0.z; d8[3] = p0.w;
            d8[4] = p1.x; d8[5] = p1.y; d8[6] = p1.z; d8[7] = p1.w;
            v = d8[0] + d8[1] + d8[2] + d8[3] + d8[4] + d8[5] + d8[6] + d8[7];
        }
        int x = v;
        #pragma unroll
        for (int off = 1; off < 32; off <<= 1) {
            int t = __shfl_up_sync(0xFFFFFFFF, x, off);
            if (lane >= off) x += t;
        }
        if (lane == 31) wsum[wid] = x;
        __syncthreads();
        if (wid == 0) {
            int s = wsum[lane];
            #pragma unroll
            for (int off = 1; off < 32; off <<= 1) {
                int t = __shfl_up_sync(0xFFFFFFFF, s, off);
                if (lane >= off) s += t;
            }
            wsum[lane] = s;
        }
        __syncthreads();
        int excl = x - v + (wid > 0 ? wsum[wid - 1] : 0);
        int total = wsum[31];
        if (i < NNODES) {
            int off = carry + excl;
            int rp[8];
            #pragma unroll
            for (int r = 0; r < 8; r++) { rp[r] = off; off += d8[r]; }
            *reinterpret_cast<int4*>(&g_rowptr8[i * 8])     = make_int4(rp[0], rp[1], rp[2], rp[3]);
            *reinterpret_cast<int4*>(&g_rowptr8[i * 8 + 4]) = make_int4(rp[4], rp[5], rp[6], rp[7]);
            *reinterpret_cast<int4*>(&g_cursor8[i * 8])     = make_int4(rp[0], rp[1], rp[2], rp[3]);
            *reinterpret_cast<int4*>(&g_cursor8[i * 8 + 4]) = make_int4(rp[4], rp[5], rp[6], rp[7]);
            g_deginv[i] = 1.0f / fmaxf((float)v, 1.0f);
        }
        carry += total;
        __syncthreads();
    }
    if (tid == 0) g_rowptr8[NNODES * 8] = carry;     // == NEDGES
}

__global__ void scatter_kernel(const int* __restrict__ src,
                               const int* __restrict__ dst,
                               const int* __restrict__ rel) {
    int e = blockIdx.x * blockDim.x + threadIdx.x;
    if (e < NEDGES) {
        int pos = atomicAdd(&g_cursor8[dst[e] * NREL + rel[e]], 1);
        g_edges[pos] = src[e];
    }
}

// ---------------- weight assembly: g_W[k][o] fp32 ----------------
__global__ void wcat_kernel(const float* __restrict__ bases,
                            const float* __restrict__ coeffs,
                            const float* __restrict__ selfw,
                            int l) {
    int k = blockIdx.x;
    int o = threadIdx.x;
    if (k < 2048) {
        int r = k >> 8;
        int i = k & 255;
        const float* cf = coeffs + (l * NREL + r) * NBASES;
        const float* bs = bases + ((size_t)l * NBASES) * HID * HID + i * HID + o;
        float s = 0.f;
        #pragma unroll 6
        for (int b = 0; b < NBASES; b++)
            s += cf[b] * bs[(size_t)b * HID * HID];
        g_W[k * HID + o] = s;
    } else {
        g_W[k * HID + o] = selfw[(size_t)l * HID * HID + (k - 2048) * HID + o];
    }
}

// transpose + bf16-split into per-layer buffers
__global__ void wsplit_kernel(int l) {
    __shared__ float t[32][33];
    int k0 = blockIdx.x * 32, o0 = blockIdx.y * 32;
    int tx = threadIdx.x, ty = threadIdx.y;
    t[ty][tx] = g_W[(k0 + ty) * HID + o0 + tx];
    __syncthreads();
    float v = t[tx][ty];
    __nv_bfloat16 h = __float2bfloat16(v);
    __nv_bfloat16 lo = __float2bfloat16(v - __bfloat162float(h));
    g_Bhi[l][(size_t)(o0 + ty) * KTOT + k0 + tx] = h;
    g_Blo[l][(size_t)(o0 + ty) * KTOT + k0 + tx] = lo;
}

// ---------------- vectorized aggregation (rel-sorted CSR) -> bf16 hi/lo A rows --------
// 64 threads per node (float4 per thread), 4 nodes per 256-thread block.
// Bounds hoisted to registers; two relation segments interleaved for MLP.
__device__ __forceinline__ uint32_t pack_hi2(float a, float b, float& ra, float& rb) {
    __nv_bfloat16 ha = __float2bfloat16(a), hb = __float2bfloat16(b);
    ra = a - __bfloat162float(ha);
    rb = b - __bfloat162float(hb);
    return ((uint32_t)__bfloat16_as_ushort(hb) << 16) | (uint32_t)__bfloat16_as_ushort(ha);
}
__device__ __forceinline__ uint32_t pack_lo2(float a, float b) {
    return ((uint32_t)__bfloat16_as_ushort(__float2bfloat16(b)) << 16) |
           (uint32_t)__bfloat16_as_ushort(__float2bfloat16(a));
}
__device__ __forceinline__ void emit4(float4 v, __nv_bfloat16* hi, __nv_bfloat16* lo) {
    float r0, r1, r2, r3;
    uint2 h;
    h.x = pack_hi2(v.x, v.y, r0, r1);
    h.y = pack_hi2(v.z, v.w, r2, r3);
    uint2 l;
    l.x = pack_lo2(r0, r1);
    l.y = pack_lo2(r2, r3);
    *reinterpret_cast<uint2*>(hi) = h;
    *reinterpret_cast<uint2*>(lo) = l;
}

__global__ __launch_bounds__(256) void agg_kernel(const float* __restrict__ xin) {
    int node = (blockIdx.x << 2) + (threadIdx.x >> 6);
    if (node >= NNODES) return;
    int c4 = threadIdx.x & 63;                 // float4 column index
    const float4* x4 = reinterpret_cast<const float4*>(xin);

    // hoist all 9 segment bounds into registers
    int4 p0 = *reinterpret_cast<const int4*>(&g_rowptr8[node * 8]);
    int4 p1 = *reinterpret_cast<const int4*>(&g_rowptr8[node * 8 + 4]);
    int p8 = g_rowptr8[node * 8 + 8];
    int rp[9];
    rp[0] = p0.x; rp[1] = p0.y; rp[2] = p0.z; rp[3] = p0.w;
    rp[4] = p1.x; rp[5] = p1.y; rp[6] = p1.z; rp[7] = p1.w; rp[8] = p8;

    float dinv = g_deginv[node];
    size_t base = (size_t)node * KTOT + (c4 << 2);

    #pragma unroll
    for (int r = 0; r < 8; r += 2) {
        int ja = rp[r],     ea = rp[r + 1];
        int jb = rp[r + 1], eb = rp[r + 2];
        float4 a = make_float4(0.f, 0.f, 0.f, 0.f);
        float4 b = make_float4(0.f, 0.f, 0.f, 0.f);
        int la = ea - ja;
        int lb = eb - jb;
        int m = la < lb ? la : lb;
        #pragma unroll 2
        for (int t = 0; t < m; t++) {
            int sa = __ldg(&g_edges[ja + t]);
            int sb = __ldg(&g_edges[jb + t]);
            float4 va = __ldg(&x4[(size_t)sa * 64 + c4]);
            float4 vb = __ldg(&x4[(size_t)sb * 64 + c4]);
            a.x += va.x; a.y += va.y; a.z += va.z; a.w += va.w;
            b.x += vb.x; b.y += vb.y; b.z += vb.z; b.w += vb.w;
        }
        #pragma unroll 2
        for (int t = m; t < la; t++) {
            int sa = __ldg(&g_edges[ja + t]);
            float4 va = __ldg(&x4[(size_t)sa * 64 + c4]);
            a.x += va.x; a.y += va.y; a.z += va.z; a.w += va.w;
        }
        #pragma unroll 2
        for (int t = m; t < lb; t++) {
            int sb = __ldg(&g_edges[jb + t]);
            float4 vb = __ldg(&x4[(size_t)sb * 64 + c4]);
            b.x += vb.x; b.y += vb.y; b.z += vb.z; b.w += vb.w;
        }
        a.x *= dinv; a.y *= dinv; a.z *= dinv; a.w *= dinv;
        b.x *= dinv; b.y *= dinv; b.z *= dinv; b.w *= dinv;
        emit4(a, g_Ahi + base + r * HID,       g_Alo + base + r * HID);
        emit4(b, g_Ahi + base + (r + 1) * HID, g_Alo + base + (r + 1) * HID);
    }
    float4 self = __ldg(&x4[(size_t)node * 64 + c4]);
    emit4(self, g_Ahi + base + 2048, g_Alo + base + 2048);
}

// ---------------- HMMA GEMM: C[M,256] = (Ahi+Alo)@(Bhi+Blo)^T (3-term bf16) ----------------
#define KC 64
#define NCHUNK (KTOT / KC)     // 36
#define ST_AH 0
#define ST_AL (16 * 1024)
#define ST_BH (32 * 1024)
#define ST_BL (64 * 1024)
#define STAGE_BYTES (96 * 1024)
#define GEMM_SMEM (2 * STAGE_BYTES)

__device__ __forceinline__ void load_chunk512(uint32_t sb, int brow, int k0, int tid,
                                              const __nv_bfloat16* Ahi, const __nv_bfloat16* Alo,
                                              const __nv_bfloat16* Bhi, const __nv_bfloat16* Blo) {
    #pragma unroll
    for (int it = 0; it < 12; it++) {
        int u = tid + it * 512;
        if (u < 2048) {
            int idx = u & 1023;
            int r = idx >> 3, c = idx & 7;
            uint32_t so = SWZ128((uint32_t)(r * 128 + c * 16));
            const __nv_bfloat16* g = (u < 1024 ? Ahi : Alo) + (size_t)(brow + r) * KTOT + k0 + c * 8;
            cp16(sb + (u < 1024 ? ST_AH : ST_AL) + so, g);
        } else {
            int v = u - 2048;
            int idx = v & 2047;
            int r = idx >> 3, c = idx & 7;
            uint32_t so = SWZ128((uint32_t)(r * 128 + c * 16));
            const __nv_bfloat16* g = (v < 2048 ? Bhi : Blo) + (size_t)r * KTOT + k0 + c * 8;
            cp16(sb + (v < 2048 ? ST_BH : ST_BL) + so, g);
        }
    }
}

__global__ __launch_bounds__(512, 1) void mma_gemm_kernel(
    const __nv_bfloat16* __restrict__ Ahi, const __nv_bfloat16* __restrict__ Alo,
    const __nv_bfloat16* __restrict__ Bhi, const __nv_bfloat16* __restrict__ Blo,
    float* __restrict__ C, int m_store, int do_relu)
{
    extern __shared__ char smraw[];
    uint32_t smem_base = smem_to_u32(smraw);
    int tid = threadIdx.x;
    int wid = tid >> 5;
    int lane = tid & 31;
    int wm = wid & 3;
    int wn = wid >> 2;
    int brow = blockIdx.x * 128;

    float acc[2][8][4];
    #pragma unroll
    for (int i = 0; i < 2; i++)
        #pragma unroll
        for (int j = 0; j < 8; j++)
            #pragma unroll
            for (int q = 0; q < 4; q++) acc[i][j][q] = 0.f;

    load_chunk512(smem_base, brow, 0, tid, Ahi, Alo, Bhi, Blo);
    asm volatile("cp.async.commit_group;" ::: "memory");
    load_chunk512(smem_base + STAGE_BYTES, brow, KC, tid, Ahi, Alo, Bhi, Blo);
    asm volatile("cp.async.commit_group;" ::: "memory");

    int a_row = wm * 32 + (lane & 15);
    int a_kc8 = (lane >> 4) << 3;
    int tg = lane >> 3;
    int b_nbase = wn * 64 + ((tg >> 1) << 3) + (lane & 7);
    int b_kc8 = (tg & 1) << 3;

    for (int i = 0; i < NCHUNK; i++) {
        uint32_t sb = smem_base + (uint32_t)(i & 1) * STAGE_BYTES;
        asm volatile("cp.async.wait_group 1;" ::: "memory");
        __syncthreads();

        #pragma unroll
        for (int ks = 0; ks < 4; ks++) {
            int k = ks * 16;
            uint32_t ah[2][4], al[2][4], bh[4][4], bl[4][4];
            #pragma unroll
            for (int g = 0; g < 2; g++) {
                uint32_t bo = (uint32_t)((a_row + g * 16) * 128 + (k + a_kc8) * 2);
                ldsm4(ah[g][0], ah[g][1], ah[g][2], ah[g][3], sb + ST_AH + SWZ128(bo));
            }
            #pragma unroll
            for (int j = 0; j < 4; j++) {
                uint32_t bo = (uint32_t)((b_nbase + j * 16) * 128 + (k + b_kc8) * 2);
                ldsm4(bh[j][0], bh[j][1], bh[j][2], bh[j][3], sb + ST_BH + SWZ128(bo));
            }
            #pragma unroll
            for (int mt = 0; mt < 2; mt++)
                #pragma unroll
                for (int nt = 0; nt < 8; nt++)
                    mma16816(acc[mt][nt], ah[mt], &bh[nt >> 1][(nt & 1) * 2]);
            #pragma unroll
            for (int g = 0; g < 2; g++) {
                uint32_t bo = (uint32_t)((a_row + g * 16) * 128 + (k + a_kc8) * 2);
                ldsm4(al[g][0], al[g][1], al[g][2], al[g][3], sb + ST_AL + SWZ128(bo));
            }
            #pragma unroll
            for (int mt = 0; mt < 2; mt++)
                #pragma unroll
                for (int nt = 0; nt < 8; nt++)
                    mma16816(acc[mt][nt], al[mt], &bh[nt >> 1][(nt & 1) * 2]);
            #pragma unroll
            for (int j = 0; j < 4; j++) {
                uint32_t bo = (uint32_t)((b_nbase + j * 16) * 128 + (k + b_kc8) * 2);
                ldsm4(bl[j][0], bl[j][1], bl[j][2], bl[j][3], sb + ST_BL + SWZ128(bo));
            }
            #pragma unroll
            for (int mt = 0; mt < 2; mt++)
                #pragma unroll
                for (int nt = 0; nt < 8; nt++)
                    mma16816(acc[mt][nt], ah[mt], &bl[nt >> 1][(nt & 1) * 2]);
        }
        __syncthreads();
        if (i + 2 < NCHUNK)
            load_chunk512(sb, brow, (i + 2) * KC, tid, Ahi, Alo, Bhi, Blo);
        asm volatile("cp.async.commit_group;" ::: "memory");
    }

    int col = wn * 64 + 2 * (lane & 3);
    #pragma unroll
    for (int mt = 0; mt < 2; mt++) {
        int r0 = brow + wm * 32 + mt * 16 + (lane >> 2);
        int r1 = r0 + 8;
        #pragma unroll
        for (int nt = 0; nt < 8; nt++) {
            float2 v0 = make_float2(acc[mt][nt][0], acc[mt][nt][1]);
            float2 v1 = make_float2(acc[mt][nt][2], acc[mt][nt][3]);
            if (do_relu) {
                v0.x = fmaxf(v0.x, 0.f); v0.y = fmaxf(v0.y, 0.f);
                v1.x = fmaxf(v1.x, 0.f); v1.y = fmaxf(v1.y, 0.f);
            }
            if (r0 < m_store)
                *reinterpret_cast<float2*>(&C[(size_t)r0 * HID + col + nt * 8]) = v0;
            if (r1 < m_store)
                *reinterpret_cast<float2*>(&C[(size_t)r1 * HID + col + nt * 8]) = v1;
        }
    }
}

// ---------------- launch ----------------
extern "C" void kernel_launch(void* const* d_in, const int* in_sizes, int n_in,
                              void* d_out, int out_size) {
    const int*   edge_index = nullptr;
    const int*   edge_type  = nullptr;
    const float* emb        = nullptr;
    const float* bases      = nullptr;
    const float* coeffs     = nullptr;
    const float* selfw      = nullptr;
    for (int i = 0; i < n_in; i++) {
        switch (in_sizes[i]) {
            case 2 * NEDGES:             edge_index = (const int*)d_in[i]; break;
            case NEDGES:                 edge_type  = (const int*)d_in[i]; break;
            case NNODES * HID:           emb        = (const float*)d_in[i]; break;
            case 2 * NBASES * HID * HID: bases      = (const float*)d_in[i]; break;
            case 2 * NREL * NBASES:      coeffs     = (const float*)d_in[i]; break;
            case 2 * HID * HID:          selfw      = (const float*)d_in[i]; break;
            default: break;
        }
    }
    const int* srcp = edge_index;
    const int* dstp = edge_index + NEDGES;
    float* outp = (float*)d_out;

    static cudaStream_t s1 = nullptr;
    static cudaEvent_t e0, e1, e2;
    if (!s1) {
        cudaStreamCreateWithFlags(&s1, cudaStreamNonBlocking);
        cudaEventCreateWithFlags(&e0, cudaEventDisableTiming);
        cudaEventCreateWithFlags(&e1, cudaEventDisableTiming);
        cudaEventCreateWithFlags(&e2, cudaEventDisableTiming);
    }

    int* deg8_p;
    __nv_bfloat16 *ahi_p, *alo_p, *bhi_p, *blo_p;
    float* x1_p;
    cudaGetSymbolAddress((void**)&deg8_p, g_deg8);
    cudaGetSymbolAddress((void**)&ahi_p, g_Ahi);
    cudaGetSymbolAddress((void**)&alo_p, g_Alo);
    cudaGetSymbolAddress((void**)&bhi_p, g_Bhi);
    cudaGetSymbolAddress((void**)&blo_p, g_Blo);
    cudaGetSymbolAddress((void**)&x1_p, g_x1);

    cudaFuncSetAttribute(mma_gemm_kernel, cudaFuncAttributeMaxDynamicSharedMemorySize, GEMM_SMEM);

    dim3 wsgrid(KTOT / 32, HID / 32);
    dim3 wsblk(32, 32);
    const int AGG_BLOCKS = (NNODES + 3) / 4;     // 12500
    int ggrid = 391;

    cudaEventRecord(e0, 0);

    // stream0: CSR build (rel-sorted) + agg0
    cudaMemsetAsync(deg8_p, 0, NNODES * NREL * sizeof(int), 0);
    hist_kernel<<<(NEDGES + 255) / 256, 256>>>(dstp, edge_type);
    scan_kernel<<<1, 1024>>>();
    scatter_kernel<<<(NEDGES + 255) / 256, 256>>>(srcp, dstp, edge_type);
    agg_kernel<<<AGG_BLOCKS, 256>>>(emb);

    // s1: weight prep for both layers (overlaps CSR + agg)
    cudaStreamWaitEvent(s1, e0, 0);
    wcat_kernel<<<KTOT, HID, 0, s1>>>(bases, coeffs, selfw, 0);
    wsplit_kernel<<<wsgrid, wsblk, 0, s1>>>(0);
    cudaEventRecord(e1, s1);
    wcat_kernel<<<KTOT, HID, 0, s1>>>(bases, coeffs, selfw, 1);
    wsplit_kernel<<<wsgrid, wsblk, 0, s1>>>(1);
    cudaEventRecord(e2, s1);

    // layer 0 GEMM
    cudaStreamWaitEvent(0, e1, 0);
    mma_gemm_kernel<<<ggrid, 512, GEMM_SMEM>>>(ahi_p, alo_p, bhi_p, blo_p, x1_p, NNODES, 1);

    // layer 1
    agg_kernel<<<AGG_BLOCKS, 256>>>(x1_p);
    cudaStreamWaitEvent(0, e2, 0);
    mma_gemm_kernel<<<ggrid, 512, GEMM_SMEM>>>(ahi_p, alo_p,
                                               bhi_p + (size_t)HID * KTOT,
                                               blo_p + (size_t)HID * KTOT, outp, NNODES, 0);

    (void)out_size;
}

// round 10
// speedup vs baseline: 1.0519x; 1.0519x over previous
#include <cuda_runtime.h>
#include <cuda_bf16.h>
#include <cstdint>

// ---------------- problem constants ----------------
#define NNODES 50000
#define NEDGES 800000
#define NREL   8
#define HID    256
#define NBASES 30
#define KTOT   2304            // 8*256 relation cols + 256 self cols
#define MPAD   50176           // array padding; GEMM uses 391*128 = 50048 rows

// ---------------- device scratch (static, .bss zero-initialized) ----------------
__device__ int   g_deg8[NNODES * NREL];              // per-(node,rel) counts
__device__ float g_deginv[NNODES];
__device__ int   g_rowptr8[NNODES * NREL + 8];       // per-(node,rel) CSR offsets
__device__ int   g_cursor8[NNODES * NREL];
__device__ int   g_edges[NEDGES];                    // src only (sorted by node,rel)
__device__ __align__(256) __nv_bfloat16 g_Ahi[(size_t)MPAD * KTOT];  // pad rows stay 0
__device__ __align__(256) __nv_bfloat16 g_Alo[(size_t)MPAD * KTOT];
__device__ float g_W[KTOT * HID];                    // W[k][o] fp32 (serial on s1)
__device__ __align__(256) __nv_bfloat16 g_Bhi[2][HID * KTOT];  // per-layer W^T hi: [o][k]
__device__ __align__(256) __nv_bfloat16 g_Blo[2][HID * KTOT];  // per-layer W^T lo: [o][k]
__device__ float g_x1[(size_t)MPAD * HID];

// ================= helpers =================
__device__ __forceinline__ uint32_t smem_to_u32(const void* p) {
    uint32_t a;
    asm("{ .reg .u64 t; cvta.to.shared.u64 t, %1; cvt.u32.u64 %0, t; }" : "=r"(a) : "l"(p));
    return a;
}
#define SWZ128(off) ((off) ^ (((off) >> 3) & 0x70))

__device__ __forceinline__ void cp16(uint32_t dst, const void* src) {
    asm volatile("cp.async.cg.shared.global [%0], [%1], 16;" :: "r"(dst), "l"(src));
}
__device__ __forceinline__ void ldsm4(uint32_t& r0, uint32_t& r1, uint32_t& r2, uint32_t& r3,
                                      uint32_t addr) {
    asm volatile("ldmatrix.sync.aligned.m8n8.x4.shared.b16 {%0,%1,%2,%3}, [%4];"
                 : "=r"(r0), "=r"(r1), "=r"(r2), "=r"(r3) : "r"(addr));
}
__device__ __forceinline__ void mma16816(float* c, const uint32_t* a, const uint32_t* b) {
    asm volatile("mma.sync.aligned.m16n8k16.row.col.f32.bf16.bf16.f32 "
                 "{%0,%1,%2,%3}, {%4,%5,%6,%7}, {%8,%9}, {%0,%1,%2,%3};"
                 : "+f"(c[0]), "+f"(c[1]), "+f"(c[2]), "+f"(c[3])
                 : "r"(a[0]), "r"(a[1]), "r"(a[2]), "r"(a[3]), "r"(b[0]), "r"(b[1]));
}

// ---------------- setup kernels ----------------
__global__ void hist_kernel(const int* __restrict__ dst, const int* __restrict__ rel) {
    int e = blockIdx.x * blockDim.x + threadIdx.x;
    if (e < NEDGES) atomicAdd(&g_deg8[dst[e] * NREL + rel[e]], 1);
}

// single-block shuffle scan over node degrees; also emits per-(node,rel) offsets
__global__ void scan_kernel() {
    __shared__ int wsum[32];
    int tid = threadIdx.x;
    int lane = tid & 31;
    int wid = tid >> 5;
    int carry = 0;
    for (int base = 0; base < NNODES; base += 1024) {
        int i = base + tid;
        int d8[8];
        int v = 0;
        if (i < NNODES) {
            int4 p0 = *reinterpret_cast<const int4*>(&g_deg8[i * 8]);
            int4 p1 = *reinterpret_cast<const int4*>(&g_deg8[i * 8 + 4]);
            d8[0] = p0.x; d8[1] = p0.y; d8[2] = p0.z; d8[3] = p0.w;
            d8[4] = p1.x; d8[5] = p1.y; d8[6] = p1.z; d8[7] = p1.w;
            v = d8[0] + d8[1] + d8[2] + d8[3] + d8[4] + d8[5] + d8[6] + d8[7];
        }
        int x = v;
        #pragma unroll
        for (int off = 1; off < 32; off <<= 1) {
            int t = __shfl_up_sync(0xFFFFFFFF, x, off);
            if (lane >= off) x += t;
        }
        if (lane == 31) wsum[wid] = x;
        __syncthreads();
        if (wid == 0) {
            int s = wsum[lane];
            #pragma unroll
            for (int off = 1; off < 32; off <<= 1) {
                int t = __shfl_up_sync(0xFFFFFFFF, s, off);
                if (lane >= off) s += t;
            }
            wsum[lane] = s;
        }
        __syncthreads();
        int excl = x - v + (wid > 0 ? wsum[wid - 1] : 0);
        int total = wsum[31];
        if (i < NNODES) {
            int off = carry + excl;
            int rp[8];
            #pragma unroll
            for (int r = 0; r < 8; r++) { rp[r] = off; off += d8[r]; }
            *reinterpret_cast<int4*>(&g_rowptr8[i * 8])     = make_int4(rp[0], rp[1], rp[2], rp[3]);
            *reinterpret_cast<int4*>(&g_rowptr8[i * 8 + 4]) = make_int4(rp[4], rp[5], rp[6], rp[7]);
            *reinterpret_cast<int4*>(&g_cursor8[i * 8])     = make_int4(rp[0], rp[1], rp[2], rp[3]);
            *reinterpret_cast<int4*>(&g_cursor8[i * 8 + 4]) = make_int4(rp[4], rp[5], rp[6], rp[7]);
            g_deginv[i] = 1.0f / fmaxf((float)v, 1.0f);
        }
        carry += total;
        __syncthreads();
    }
    if (tid == 0) g_rowptr8[NNODES * 8] = carry;     // == NEDGES
}

__global__ void scatter_kernel(const int* __restrict__ src,
                               const int* __restrict__ dst,
                               const int* __restrict__ rel) {
    int e = blockIdx.x * blockDim.x + threadIdx.x;
    if (e < NEDGES) {
        int pos = atomicAdd(&g_cursor8[dst[e] * NREL + rel[e]], 1);
        g_edges[pos] = src[e];
    }
}

// ---------------- weight assembly: g_W[k][o] fp32 ----------------
__global__ void wcat_kernel(const float* __restrict__ bases,
                            const float* __restrict__ coeffs,
                            const float* __restrict__ selfw,
                            int l) {
    int k = blockIdx.x;
    int o = threadIdx.x;
    if (k < 2048) {
        int r = k >> 8;
        int i = k & 255;
        const float* cf = coeffs + (l * NREL + r) * NBASES;
        const float* bs = bases + ((size_t)l * NBASES) * HID * HID + i * HID + o;
        float s = 0.f;
        #pragma unroll 6
        for (int b = 0; b < NBASES; b++)
            s += cf[b] * bs[(size_t)b * HID * HID];
        g_W[k * HID + o] = s;
    } else {
        g_W[k * HID + o] = selfw[(size_t)l * HID * HID + (k - 2048) * HID + o];
    }
}

// transpose + bf16-split into per-layer buffers
__global__ void wsplit_kernel(int l) {
    __shared__ float t[32][33];
    int k0 = blockIdx.x * 32, o0 = blockIdx.y * 32;
    int tx = threadIdx.x, ty = threadIdx.y;
    t[ty][tx] = g_W[(k0 + ty) * HID + o0 + tx];
    __syncthreads();
    float v = t[tx][ty];
    __nv_bfloat16 h = __float2bfloat16(v);
    __nv_bfloat16 lo = __float2bfloat16(v - __bfloat162float(h));
    g_Bhi[l][(size_t)(o0 + ty) * KTOT + k0 + tx] = h;
    g_Blo[l][(size_t)(o0 + ty) * KTOT + k0 + tx] = lo;
}

// ---------------- vectorized aggregation (rel-sorted CSR) -> bf16 hi/lo A rows --------
// R8 version: 64 threads/node, one accumulator, 8 sequential segments. 30 regs.
__device__ __forceinline__ uint32_t pack_hi2(float a, float b, float& ra, float& rb) {
    __nv_bfloat16 ha = __float2bfloat16(a), hb = __float2bfloat16(b);
    ra = a - __bfloat162float(ha);
    rb = b - __bfloat162float(hb);
    return ((uint32_t)__bfloat16_as_ushort(hb) << 16) | (uint32_t)__bfloat16_as_ushort(ha);
}
__device__ __forceinline__ uint32_t pack_lo2(float a, float b) {
    return ((uint32_t)__bfloat16_as_ushort(__float2bfloat16(b)) << 16) |
           (uint32_t)__bfloat16_as_ushort(__float2bfloat16(a));
}
__device__ __forceinline__ void emit4(float4 v, __nv_bfloat16* hi, __nv_bfloat16* lo) {
    float r0, r1, r2, r3;
    uint2 h;
    h.x = pack_hi2(v.x, v.y, r0, r1);
    h.y = pack_hi2(v.z, v.w, r2, r3);
    uint2 l;
    l.x = pack_lo2(r0, r1);
    l.y = pack_lo2(r2, r3);
    *reinterpret_cast<uint2*>(hi) = h;
    *reinterpret_cast<uint2*>(lo) = l;
}

__global__ __launch_bounds__(256) void agg_kernel(const float* __restrict__ xin,
                                                  int emit_self) {
    int node = (blockIdx.x << 2) + (threadIdx.x >> 6);
    if (node >= NNODES) return;
    int c4 = threadIdx.x & 63;                 // float4 column index
    const float4* x4 = reinterpret_cast<const float4*>(xin);
    float dinv = g_deginv[node];
    size_t base = (size_t)node * KTOT + (c4 << 2);

    int j0 = g_rowptr8[node * 8];
    #pragma unroll 1
    for (int r = 0; r < 8; r++) {
        int j1 = g_rowptr8[node * 8 + r + 1];
        float4 a = make_float4(0.f, 0.f, 0.f, 0.f);
        #pragma unroll 2
        for (int j = j0; j < j1; j++) {
            int s = __ldg(&g_edges[j]);
            float4 v = __ldg(&x4[(size_t)s * 64 + c4]);
            a.x += v.x; a.y += v.y; a.z += v.z; a.w += v.w;
        }
        a.x *= dinv; a.y *= dinv; a.z *= dinv; a.w *= dinv;
        emit4(a, g_Ahi + base + r * HID, g_Alo + base + r * HID);
        j0 = j1;
    }
    if (emit_self) {
        float4 self = __ldg(&x4[(size_t)node * 64 + c4]);
        emit4(self, g_Ahi + base + 2048, g_Alo + base + 2048);
    }
}

// ---------------- HMMA GEMM: C[M,256] = (Ahi+Alo)@(Bhi+Blo)^T (3-term bf16) ----------------
// When self_split != 0, the epilogue additionally writes the bf16 hi/lo split of the
// (post-relu) output into g_Ahi/g_Alo self columns [2048..2303] for the NEXT layer.
#define KC 64
#define NCHUNK (KTOT / KC)     // 36
#define ST_AH 0
#define ST_AL (16 * 1024)
#define ST_BH (32 * 1024)
#define ST_BL (64 * 1024)
#define STAGE_BYTES (96 * 1024)
#define GEMM_SMEM (2 * STAGE_BYTES)

__device__ __forceinline__ void load_chunk512(uint32_t sb, int brow, int k0, int tid,
                                              const __nv_bfloat16* Ahi, const __nv_bfloat16* Alo,
                                              const __nv_bfloat16* Bhi, const __nv_bfloat16* Blo) {
    #pragma unroll
    for (int it = 0; it < 12; it++) {
        int u = tid + it * 512;
        if (u < 2048) {
            int idx = u & 1023;
            int r = idx >> 3, c = idx & 7;
            uint32_t so = SWZ128((uint32_t)(r * 128 + c * 16));
            const __nv_bfloat16* g = (u < 1024 ? Ahi : Alo) + (size_t)(brow + r) * KTOT + k0 + c * 8;
            cp16(sb + (u < 1024 ? ST_AH : ST_AL) + so, g);
        } else {
            int v = u - 2048;
            int idx = v & 2047;
            int r = idx >> 3, c = idx & 7;
            uint32_t so = SWZ128((uint32_t)(r * 128 + c * 16));
            const __nv_bfloat16* g = (v < 2048 ? Bhi : Blo) + (size_t)r * KTOT + k0 + c * 8;
            cp16(sb + (v < 2048 ? ST_BH : ST_BL) + so, g);
        }
    }
}

__global__ __launch_bounds__(512, 1) void mma_gemm_kernel(
    const __nv_bfloat16* __restrict__ Ahi, const __nv_bfloat16* __restrict__ Alo,
    const __nv_bfloat16* __restrict__ Bhi, const __nv_bfloat16* __restrict__ Blo,
    float* __restrict__ C, int m_store, int do_relu, int self_split)
{
    extern __shared__ char smraw[];
    uint32_t smem_base = smem_to_u32(smraw);
    int tid = threadIdx.x;
    int wid = tid >> 5;
    int lane = tid & 31;
    int wm = wid & 3;
    int wn = wid >> 2;
    int brow = blockIdx.x * 128;

    float acc[2][8][4];
    #pragma unroll
    for (int i = 0; i < 2; i++)
        #pragma unroll
        for (int j = 0; j < 8; j++)
            #pragma unroll
            for (int q = 0; q < 4; q++) acc[i][j][q] = 0.f;

    load_chunk512(smem_base, brow, 0, tid, Ahi, Alo, Bhi, Blo);
    asm volatile("cp.async.commit_group;" ::: "memory");
    load_chunk512(smem_base + STAGE_BYTES, brow, KC, tid, Ahi, Alo, Bhi, Blo);
    asm volatile("cp.async.commit_group;" ::: "memory");

    int a_row = wm * 32 + (lane & 15);
    int a_kc8 = (lane >> 4) << 3;
    int tg = lane >> 3;
    int b_nbase = wn * 64 + ((tg >> 1) << 3) + (lane & 7);
    int b_kc8 = (tg & 1) << 3;

    for (int i = 0; i < NCHUNK; i++) {
        uint32_t sb = smem_base + (uint32_t)(i & 1) * STAGE_BYTES;
        asm volatile("cp.async.wait_group 1;" ::: "memory");
        __syncthreads();

        #pragma unroll
        for (int ks = 0; ks < 4; ks++) {
            int k = ks * 16;
            uint32_t ah[2][4], al[2][4], bh[4][4], bl[4][4];
            #pragma unroll
            for (int g = 0; g < 2; g++) {
                uint32_t bo = (uint32_t)((a_row + g * 16) * 128 + (k + a_kc8) * 2);
                ldsm4(ah[g][0], ah[g][1], ah[g][2], ah[g][3], sb + ST_AH + SWZ128(bo));
            }
            #pragma unroll
            for (int j = 0; j < 4; j++) {
                uint32_t bo = (uint32_t)((b_nbase + j * 16) * 128 + (k + b_kc8) * 2);
                ldsm4(bh[j][0], bh[j][1], bh[j][2], bh[j][3], sb + ST_BH + SWZ128(bo));
            }
            #pragma unroll
            for (int mt = 0; mt < 2; mt++)
                #pragma unroll
                for (int nt = 0; nt < 8; nt++)
                    mma16816(acc[mt][nt], ah[mt], &bh[nt >> 1][(nt & 1) * 2]);
            #pragma unroll
            for (int g = 0; g < 2; g++) {
                uint32_t bo = (uint32_t)((a_row + g * 16) * 128 + (k + a_kc8) * 2);
                ldsm4(al[g][0], al[g][1], al[g][2], al[g][3], sb + ST_AL + SWZ128(bo));
            }
            #pragma unroll
            for (int mt = 0; mt < 2; mt++)
                #pragma unroll
                for (int nt = 0; nt < 8; nt++)
                    mma16816(acc[mt][nt], al[mt], &bh[nt >> 1][(nt & 1) * 2]);
            #pragma unroll
            for (int j = 0; j < 4; j++) {
                uint32_t bo = (uint32_t)((b_nbase + j * 16) * 128 + (k + b_kc8) * 2);
                ldsm4(bl[j][0], bl[j][1], bl[j][2], bl[j][3], sb + ST_BL + SWZ128(bo));
            }
            #pragma unroll
            for (int mt = 0; mt < 2; mt++)
                #pragma unroll
                for (int nt = 0; nt < 8; nt++)
                    mma16816(acc[mt][nt], ah[mt], &bl[nt >> 1][(nt & 1) * 2]);
        }
        __syncthreads();
        if (i + 2 < NCHUNK)
            load_chunk512(sb, brow, (i + 2) * KC, tid, Ahi, Alo, Bhi, Blo);
        asm volatile("cp.async.commit_group;" ::: "memory");
    }

    int col = wn * 64 + 2 * (lane & 3);
    #pragma unroll
    for (int mt = 0; mt < 2; mt++) {
        int r0 = brow + wm * 32 + mt * 16 + (lane >> 2);
        int r1 = r0 + 8;
        #pragma unroll
        for (int nt = 0; nt < 8; nt++) {
            float2 v0 = make_float2(acc[mt][nt][0], acc[mt][nt][1]);
            float2 v1 = make_float2(acc[mt][nt][2], acc[mt][nt][3]);
            if (do_relu) {
                v0.x = fmaxf(v0.x, 0.f); v0.y = fmaxf(v0.y, 0.f);
                v1.x = fmaxf(v1.x, 0.f); v1.y = fmaxf(v1.y, 0.f);
            }
            int c = col + nt * 8;
            if (r0 < m_store) {
                *reinterpret_cast<float2*>(&C[(size_t)r0 * HID + c]) = v0;
                if (self_split) {
                    float q0, q1;
                    uint32_t h = pack_hi2(v0.x, v0.y, q0, q1);
                    uint32_t l = pack_lo2(q0, q1);
                    *reinterpret_cast<uint32_t*>(&g_Ahi[(size_t)r0 * KTOT + 2048 + c]) = h;
                    *reinterpret_cast<uint32_t*>(&g_Alo[(size_t)r0 * KTOT + 2048 + c]) = l;
                }
            }
            if (r1 < m_store) {
                *reinterpret_cast<float2*>(&C[(size_t)r1 * HID + c]) = v1;
                if (self_split) {
                    float q0, q1;
                    uint32_t h = pack_hi2(v1.x, v1.y, q0, q1);
                    uint32_t l = pack_lo2(q0, q1);
                    *reinterpret_cast<uint32_t*>(&g_Ahi[(size_t)r1 * KTOT + 2048 + c]) = h;
                    *reinterpret_cast<uint32_t*>(&g_Alo[(size_t)r1 * KTOT + 2048 + c]) = l;
                }
            }
        }
    }
}

// ---------------- launch ----------------
extern "C" void kernel_launch(void* const* d_in, const int* in_sizes, int n_in,
                              void* d_out, int out_size) {
    const int*   edge_index = nullptr;
    const int*   edge_type  = nullptr;
    const float* emb        = nullptr;
    const float* bases      = nullptr;
    const float* coeffs     = nullptr;
    const float* selfw      = nullptr;
    for (int i = 0; i < n_in; i++) {
        switch (in_sizes[i]) {
            case 2 * NEDGES:             edge_index = (const int*)d_in[i]; break;
            case NEDGES:                 edge_type  = (const int*)d_in[i]; break;
            case NNODES * HID:           emb        = (const float*)d_in[i]; break;
            case 2 * NBASES * HID * HID: bases      = (const float*)d_in[i]; break;
            case 2 * NREL * NBASES:      coeffs     = (const float*)d_in[i]; break;
            case 2 * HID * HID:          selfw      = (const float*)d_in[i]; break;
            default: break;
        }
    }
    const int* srcp = edge_index;
    const int* dstp = edge_index + NEDGES;
    float* outp = (float*)d_out;

    static cudaStream_t s1 = nullptr;
    static cudaEvent_t e0, e1, e2;
    if (!s1) {
        cudaStreamCreateWithFlags(&s1, cudaStreamNonBlocking);
        cudaEventCreateWithFlags(&e0, cudaEventDisableTiming);
        cudaEventCreateWithFlags(&e1, cudaEventDisableTiming);
        cudaEventCreateWithFlags(&e2, cudaEventDisableTiming);
    }

    int* deg8_p;
    __nv_bfloat16 *ahi_p, *alo_p, *bhi_p, *blo_p;
    float* x1_p;
    cudaGetSymbolAddress((void**)&deg8_p, g_deg8);
    cudaGetSymbolAddress((void**)&ahi_p, g_Ahi);
    cudaGetSymbolAddress((void**)&alo_p, g_Alo);
    cudaGetSymbolAddress((void**)&bhi_p, g_Bhi);
    cudaGetSymbolAddress((void**)&blo_p, g_Blo);
    cudaGetSymbolAddress((void**)&x1_p, g_x1);

    cudaFuncSetAttribute(mma_gemm_kernel, cudaFuncAttributeMaxDynamicSharedMemorySize, GEMM_SMEM);

    dim3 wsgrid(KTOT / 32, HID / 32);
    dim3 wsblk(32, 32);
    const int AGG_BLOCKS = (NNODES + 3) / 4;     // 12500
    int ggrid = 391;

    cudaEventRecord(e0, 0);

    // stream0: CSR build (rel-sorted) + agg0
    cudaMemsetAsync(deg8_p, 0, NNODES * NREL * sizeof(int), 0);
    hist_kernel<<<(NEDGES + 255) / 256, 256>>>(dstp, edge_type);
    scan_kernel<<<1, 1024>>>();
    scatter_kernel<<<(NEDGES + 255) / 256, 256>>>(srcp, dstp, edge_type);
    agg_kernel<<<AGG_BLOCKS, 256>>>(emb, 1);

    // s1: weight prep for both layers (overlaps CSR + agg)
    cudaStreamWaitEvent(s1, e0, 0);
    wcat_kernel<<<KTOT, HID, 0, s1>>>(bases, coeffs, selfw, 0);
    wsplit_kernel<<<wsgrid, wsblk, 0, s1>>>(0);
    cudaEventRecord(e1, s1);
    wcat_kernel<<<KTOT, HID, 0, s1>>>(bases, coeffs, selfw, 1);
    wsplit_kernel<<<wsgrid, wsblk, 0, s1>>>(1);
    cudaEventRecord(e2, s1);

    // layer 0 GEMM (also emits self hi/lo columns for layer 1)
    cudaStreamWaitEvent(0, e1, 0);
    mma_gemm_kernel<<<ggrid, 512, GEMM_SMEM>>>(ahi_p, alo_p, bhi_p, blo_p, x1_p, NNODES, 1, 1);

    // layer 1 (agg skips self emit — GEMM0 already wrote it)
    agg_kernel<<<AGG_BLOCKS, 256>>>(x1_p, 0);
    cudaStreamWaitEvent(0, e2, 0);
    mma_gemm_kernel<<<ggrid, 512, GEMM_SMEM>>>(ahi_p, alo_p,
                                               bhi_p + (size_t)HID * KTOT,
                                               blo_p + (size_t)HID * KTOT, outp, NNODES, 0, 0);

    (void)out_size;
}

// round 11
// speedup vs baseline: 1.3416x; 1.2753x over previous
#include <cuda_runtime.h>
#include <cuda_fp16.h>
#include <cstdint>

// ---------------- problem constants ----------------
#define NNODES 50000
#define NEDGES 800000
#define NREL   8
#define HID    256
#define NBASES 30
#define KTOT   2304            // 8*256 relation cols + 256 self cols
#define MPAD   50176           // array padding; GEMM uses 391*128 = 50048 rows

// ---------------- device scratch (static, .bss zero-initialized) ----------------
__device__ int   g_deg8[NNODES * NREL];              // per-(node,rel) counts
__device__ float g_deginv[NNODES];
__device__ int   g_rowptr8[NNODES * NREL + 8];       // per-(node,rel) CSR offsets
__device__ int   g_cursor8[NNODES * NREL];
__device__ int   g_edges[NEDGES];                    // src only (sorted by node,rel)
__device__ __align__(256) __half g_Ahi[(size_t)MPAD * KTOT];  // pad rows stay 0
__device__ __align__(256) __half g_Alo[(size_t)MPAD * KTOT];
__device__ float g_W[KTOT * HID];                    // W[k][o] fp32 (serial on s1)
__device__ __align__(256) __half g_Bh[2][HID * KTOT];  // per-layer W^T fp16: [o][k]
__device__ float g_x1[(size_t)MPAD * HID];

// ================= helpers =================
__device__ __forceinline__ uint32_t smem_to_u32(const void* p) {
    uint32_t a;
    asm("{ .reg .u64 t; cvta.to.shared.u64 t, %1; cvt.u32.u64 %0, t; }" : "=r"(a) : "l"(p));
    return a;
}
#define SWZ128(off) ((off) ^ (((off) >> 3) & 0x70))

__device__ __forceinline__ void cp16(uint32_t dst, const void* src) {
    asm volatile("cp.async.cg.shared.global [%0], [%1], 16;" :: "r"(dst), "l"(src));
}
__device__ __forceinline__ void ldsm4(uint32_t& r0, uint32_t& r1, uint32_t& r2, uint32_t& r3,
                                      uint32_t addr) {
    asm volatile("ldmatrix.sync.aligned.m8n8.x4.shared.b16 {%0,%1,%2,%3}, [%4];"
                 : "=r"(r0), "=r"(r1), "=r"(r2), "=r"(r3) : "r"(addr));
}
__device__ __forceinline__ void mma16816(float* c, const uint32_t* a, const uint32_t* b) {
    asm volatile("mma.sync.aligned.m16n8k16.row.col.f32.f16.f16.f32 "
                 "{%0,%1,%2,%3}, {%4,%5,%6,%7}, {%8,%9}, {%0,%1,%2,%3};"
                 : "+f"(c[0]), "+f"(c[1]), "+f"(c[2]), "+f"(c[3])
                 : "r"(a[0]), "r"(a[1]), "r"(a[2]), "r"(a[3]), "r"(b[0]), "r"(b[1]));
}

// ---------------- setup kernels ----------------
__global__ void hist_kernel(const int* __restrict__ dst, const int* __restrict__ rel) {
    int e = blockIdx.x * blockDim.x + threadIdx.x;
    if (e < NEDGES) atomicAdd(&g_deg8[dst[e] * NREL + rel[e]], 1);
}

// single-block shuffle scan over node degrees; also emits per-(node,rel) offsets
__global__ void scan_kernel() {
    __shared__ int wsum[32];
    int tid = threadIdx.x;
    int lane = tid & 31;
    int wid = tid >> 5;
    int carry = 0;
    for (int base = 0; base < NNODES; base += 1024) {
        int i = base + tid;
        int d8[8];
        int v = 0;
        if (i < NNODES) {
            int4 p0 = *reinterpret_cast<const int4*>(&g_deg8[i * 8]);
            int4 p1 = *reinterpret_cast<const int4*>(&g_deg8[i * 8 + 4]);
            d8[0] = p0.x; d8[1] = p0.y; d8[2] = p0.z; d8[3] = p0.w;
            d8[4] = p1.x; d8[5] = p1.y; d8[6] = p1.z; d8[7] = p1.w;
            v = d8[0] + d8[1] + d8[2] + d8[3] + d8[4] + d8[5] + d8[6] + d8[7];
        }
        int x = v;
        #pragma unroll
        for (int off = 1; off < 32; off <<= 1) {
            int t = __shfl_up_sync(0xFFFFFFFF, x, off);
            if (lane >= off) x += t;
        }
        if (lane == 31) wsum[wid] = x;
        __syncthreads();
        if (wid == 0) {
            int s = wsum[lane];
            #pragma unroll
            for (int off = 1; off < 32; off <<= 1) {
                int t = __shfl_up_sync(0xFFFFFFFF, s, off);
                if (lane >= off) s += t;
            }
            wsum[lane] = s;
        }
        __syncthreads();
        int excl = x - v + (wid > 0 ? wsum[wid - 1] : 0);
        int total = wsum[31];
        if (i < NNODES) {
            int off = carry + excl;
            int rp[8];
            #pragma unroll
            for (int r = 0; r < 8; r++) { rp[r] = off; off += d8[r]; }
            *reinterpret_cast<int4*>(&g_rowptr8[i * 8])     = make_int4(rp[0], rp[1], rp[2], rp[3]);
            *reinterpret_cast<int4*>(&g_rowptr8[i * 8 + 4]) = make_int4(rp[4], rp[5], rp[6], rp[7]);
            *reinterpret_cast<int4*>(&g_cursor8[i * 8])     = make_int4(rp[0], rp[1], rp[2], rp[3]);
            *reinterpret_cast<int4*>(&g_cursor8[i * 8 + 4]) = make_int4(rp[4], rp[5], rp[6], rp[7]);
            g_deginv[i] = 1.0f / fmaxf((float)v, 1.0f);
        }
        carry += total;
        __syncthreads();
    }
    if (tid == 0) g_rowptr8[NNODES * 8] = carry;     // == NEDGES
}

__global__ void scatter_kernel(const int* __restrict__ src,
                               const int* __restrict__ dst,
                               const int* __restrict__ rel) {
    int e = blockIdx.x * blockDim.x + threadIdx.x;
    if (e < NEDGES) {
        int pos = atomicAdd(&g_cursor8[dst[e] * NREL + rel[e]], 1);
        g_edges[pos] = src[e];
    }
}

// ---------------- weight assembly: g_W[k][o] fp32 ----------------
__global__ void wcat_kernel(const float* __restrict__ bases,
                            const float* __restrict__ coeffs,
                            const float* __restrict__ selfw,
                            int l) {
    int k = blockIdx.x;
    int o = threadIdx.x;
    if (k < 2048) {
        int r = k >> 8;
        int i = k & 255;
        const float* cf = coeffs + (l * NREL + r) * NBASES;
        const float* bs = bases + ((size_t)l * NBASES) * HID * HID + i * HID + o;
        float s = 0.f;
        #pragma unroll 6
        for (int b = 0; b < NBASES; b++)
            s += cf[b] * bs[(size_t)b * HID * HID];
        g_W[k * HID + o] = s;
    } else {
        g_W[k * HID + o] = selfw[(size_t)l * HID * HID + (k - 2048) * HID + o];
    }
}

// transpose + fp16 convert into per-layer buffer (B single fp16)
__global__ void wsplit_kernel(int l) {
    __shared__ float t[32][33];
    int k0 = blockIdx.x * 32, o0 = blockIdx.y * 32;
    int tx = threadIdx.x, ty = threadIdx.y;
    t[ty][tx] = g_W[(k0 + ty) * HID + o0 + tx];
    __syncthreads();
    float v = t[tx][ty];
    g_Bh[l][(size_t)(o0 + ty) * KTOT + k0 + tx] = __float2half_rn(v);
}

// ---------------- vectorized aggregation (rel-sorted CSR) -> fp16 hi/lo A rows --------
// 64 threads/node, one accumulator, 8 sequential segments (R8 structure, fp16 emit).
__device__ __forceinline__ uint32_t pack_hi2h(float a, float b, float& ra, float& rb) {
    __half ha = __float2half_rn(a), hb = __float2half_rn(b);
    ra = a - __half2float(ha);
    rb = b - __half2float(hb);
    __half2 h = __halves2half2(ha, hb);
    return *reinterpret_cast<uint32_t*>(&h);
}
__device__ __forceinline__ uint32_t pack_lo2h(float a, float b) {
    __half2 h = __halves2half2(__float2half_rn(a), __float2half_rn(b));
    return *reinterpret_cast<uint32_t*>(&h);
}
__device__ __forceinline__ void emit4(float4 v, __half* hi, __half* lo) {
    float r0, r1, r2, r3;
    uint2 h;
    h.x = pack_hi2h(v.x, v.y, r0, r1);
    h.y = pack_hi2h(v.z, v.w, r2, r3);
    uint2 l;
    l.x = pack_lo2h(r0, r1);
    l.y = pack_lo2h(r2, r3);
    *reinterpret_cast<uint2*>(hi) = h;
    *reinterpret_cast<uint2*>(lo) = l;
}

__global__ __launch_bounds__(256) void agg_kernel(const float* __restrict__ xin) {
    int node = (blockIdx.x << 2) + (threadIdx.x >> 6);
    if (node >= NNODES) return;
    int c4 = threadIdx.x & 63;                 // float4 column index
    const float4* x4 = reinterpret_cast<const float4*>(xin);
    float dinv = g_deginv[node];
    size_t base = (size_t)node * KTOT + (c4 << 2);

    int j0 = g_rowptr8[node * 8];
    #pragma unroll 1
    for (int r = 0; r < 8; r++) {
        int j1 = g_rowptr8[node * 8 + r + 1];
        float4 a = make_float4(0.f, 0.f, 0.f, 0.f);
        #pragma unroll 2
        for (int j = j0; j < j1; j++) {
            int s = __ldg(&g_edges[j]);
            float4 v = __ldg(&x4[(size_t)s * 64 + c4]);
            a.x += v.x; a.y += v.y; a.z += v.z; a.w += v.w;
        }
        a.x *= dinv; a.y *= dinv; a.z *= dinv; a.w *= dinv;
        emit4(a, g_Ahi + base + r * HID, g_Alo + base + r * HID);
        j0 = j1;
    }
    float4 self = __ldg(&x4[(size_t)node * 64 + c4]);
    emit4(self, g_Ahi + base + 2048, g_Alo + base + 2048);
}

// ---------------- HMMA GEMM: C[M,256] = (Ahi+Alo)@Bh^T (2-pass fp16) ----------------
#define KC 64
#define NCHUNK (KTOT / KC)     // 36
#define ST_AH 0
#define ST_AL (16 * 1024)
#define ST_BH (32 * 1024)
#define STAGE_BYTES (64 * 1024)
#define GEMM_SMEM (2 * STAGE_BYTES)

__device__ __forceinline__ void load_chunk512(uint32_t sb, int brow, int k0, int tid,
                                              const __half* Ahi, const __half* Alo,
                                              const __half* Bh) {
    // A hi/lo: 2×1024 16B-units; B: 2048 units (256 rows x 8 chunks). 8 units/thread.
    #pragma unroll
    for (int it = 0; it < 8; it++) {
        int u = tid + it * 512;
        if (u < 2048) {
            int idx = u & 1023;
            int r = idx >> 3, c = idx & 7;
            uint32_t so = SWZ128((uint32_t)(r * 128 + c * 16));
            const __half* g = (u < 1024 ? Ahi : Alo) + (size_t)(brow + r) * KTOT + k0 + c * 8;
            cp16(sb + (u < 1024 ? ST_AH : ST_AL) + so, g);
        } else {
            int idx = u - 2048;                 // 0..2047
            int r = idx >> 3, c = idx & 7;
            uint32_t so = SWZ128((uint32_t)(r * 128 + c * 16));
            cp16(sb + ST_BH + so, Bh + (size_t)r * KTOT + k0 + c * 8);
        }
    }
}

__global__ __launch_bounds__(512, 1) void mma_gemm_kernel(
    const __half* __restrict__ Ahi, const __half* __restrict__ Alo,
    const __half* __restrict__ Bh,
    float* __restrict__ C, int m_store, int do_relu)
{
    extern __shared__ char smraw[];
    uint32_t smem_base = smem_to_u32(smraw);
    int tid = threadIdx.x;
    int wid = tid >> 5;
    int lane = tid & 31;
    int wm = wid & 3;
    int wn = wid >> 2;
    int brow = blockIdx.x * 128;

    float acc[2][8][4];
    #pragma unroll
    for (int i = 0; i < 2; i++)
        #pragma unroll
        for (int j = 0; j < 8; j++)
            #pragma unroll
            for (int q = 0; q < 4; q++) acc[i][j][q] = 0.f;

    load_chunk512(smem_base, brow, 0, tid, Ahi, Alo, Bh);
    asm volatile("cp.async.commit_group;" ::: "memory");
    load_chunk512(smem_base + STAGE_BYTES, brow, KC, tid, Ahi, Alo, Bh);
    asm volatile("cp.async.commit_group;" ::: "memory");

    int a_row = wm * 32 + (lane & 15);
    int a_kc8 = (lane >> 4) << 3;
    int tg = lane >> 3;
    int b_nbase = wn * 64 + ((tg >> 1) << 3) + (lane & 7);
    int b_kc8 = (tg & 1) << 3;

    for (int i = 0; i < NCHUNK; i++) {
        uint32_t sb = smem_base + (uint32_t)(i & 1) * STAGE_BYTES;
        asm volatile("cp.async.wait_group 1;" ::: "memory");
        __syncthreads();

        #pragma unroll
        for (int ks = 0; ks < 4; ks++) {
            int k = ks * 16;
            uint32_t ah[2][4], al[2][4], bh[4][4];
            #pragma unroll
            for (int g = 0; g < 2; g++) {
                uint32_t bo = (uint32_t)((a_row + g * 16) * 128 + (k + a_kc8) * 2);
                ldsm4(ah[g][0], ah[g][1], ah[g][2], ah[g][3], sb + ST_AH + SWZ128(bo));
            }
            #pragma unroll
            for (int j = 0; j < 4; j++) {
                uint32_t bo = (uint32_t)((b_nbase + j * 16) * 128 + (k + b_kc8) * 2);
                ldsm4(bh[j][0], bh[j][1], bh[j][2], bh[j][3], sb + ST_BH + SWZ128(bo));
            }
            // pass 1: Ahi x B
            #pragma unroll
            for (int mt = 0; mt < 2; mt++)
                #pragma unroll
                for (int nt = 0; nt < 8; nt++)
                    mma16816(acc[mt][nt], ah[mt], &bh[nt >> 1][(nt & 1) * 2]);
            // pass 2: Alo x B
            #pragma unroll
            for (int g = 0; g < 2; g++) {
                uint32_t bo = (uint32_t)((a_row + g * 16) * 128 + (k + a_kc8) * 2);
                ldsm4(al[g][0], al[g][1], al[g][2], al[g][3], sb + ST_AL + SWZ128(bo));
            }
            #pragma unroll
            for (int mt = 0; mt < 2; mt++)
                #pragma unroll
                for (int nt = 0; nt < 8; nt++)
                    mma16816(acc[mt][nt], al[mt], &bh[nt >> 1][(nt & 1) * 2]);
        }
        __syncthreads();
        if (i + 2 < NCHUNK)
            load_chunk512(sb, brow, (i + 2) * KC, tid, Ahi, Alo, Bh);
        asm volatile("cp.async.commit_group;" ::: "memory");
    }

    int col = wn * 64 + 2 * (lane & 3);
    #pragma unroll
    for (int mt = 0; mt < 2; mt++) {
        int r0 = brow + wm * 32 + mt * 16 + (lane >> 2);
        int r1 = r0 + 8;
        #pragma unroll
        for (int nt = 0; nt < 8; nt++) {
            float2 v0 = make_float2(acc[mt][nt][0], acc[mt][nt][1]);
            float2 v1 = make_float2(acc[mt][nt][2], acc[mt][nt][3]);
            if (do_relu) {
                v0.x = fmaxf(v0.x, 0.f); v0.y = fmaxf(v0.y, 0.f);
                v1.x = fmaxf(v1.x, 0.f); v1.y = fmaxf(v1.y, 0.f);
            }
            if (r0 < m_store)
                *reinterpret_cast<float2*>(&C[(size_t)r0 * HID + col + nt * 8]) = v0;
            if (r1 < m_store)
                *reinterpret_cast<float2*>(&C[(size_t)r1 * HID + col + nt * 8]) = v1;
        }
    }
}

// ---------------- launch ----------------
extern "C" void kernel_launch(void* const* d_in, const int* in_sizes, int n_in,
                              void* d_out, int out_size) {
    const int*   edge_index = nullptr;
    const int*   edge_type  = nullptr;
    const float* emb        = nullptr;
    const float* bases      = nullptr;
    const float* coeffs     = nullptr;
    const float* selfw      = nullptr;
    for (int i = 0; i < n_in; i++) {
        switch (in_sizes[i]) {
            case 2 * NEDGES:             edge_index = (const int*)d_in[i]; break;
            case NEDGES:                 edge_type  = (const int*)d_in[i]; break;
            case NNODES * HID:           emb        = (const float*)d_in[i]; break;
            case 2 * NBASES * HID * HID: bases      = (const float*)d_in[i]; break;
            case 2 * NREL * NBASES:      coeffs     = (const float*)d_in[i]; break;
            case 2 * HID * HID:          selfw      = (const float*)d_in[i]; break;
            default: break;
        }
    }
    const int* srcp = edge_index;
    const int* dstp = edge_index + NEDGES;
    float* outp = (float*)d_out;

    static cudaStream_t s1 = nullptr;
    static cudaEvent_t e0, e1, e2;
    if (!s1) {
        cudaStreamCreateWithFlags(&s1, cudaStreamNonBlocking);
        cudaEventCreateWithFlags(&e0, cudaEventDisableTiming);
        cudaEventCreateWithFlags(&e1, cudaEventDisableTiming);
        cudaEventCreateWithFlags(&e2, cudaEventDisableTiming);
    }

    int* deg8_p;
    __half *ahi_p, *alo_p, *bh_p;
    float* x1_p;
    cudaGetSymbolAddress((void**)&deg8_p, g_deg8);
    cudaGetSymbolAddress((void**)&ahi_p, g_Ahi);
    cudaGetSymbolAddress((void**)&alo_p, g_Alo);
    cudaGetSymbolAddress((void**)&bh_p, g_Bh);
    cudaGetSymbolAddress((void**)&x1_p, g_x1);

    cudaFuncSetAttribute(mma_gemm_kernel, cudaFuncAttributeMaxDynamicSharedMemorySize, GEMM_SMEM);

    dim3 wsgrid(KTOT / 32, HID / 32);
    dim3 wsblk(32, 32);
    const int AGG_BLOCKS = (NNODES + 3) / 4;     // 12500
    int ggrid = 391;

    cudaEventRecord(e0, 0);

    // stream0: CSR build (rel-sorted) + agg0
    cudaMemsetAsync(deg8_p, 0, NNODES * NREL * sizeof(int), 0);
    hist_kernel<<<(NEDGES + 255) / 256, 256>>>(dstp, edge_type);
    scan_kernel<<<1, 1024>>>();
    scatter_kernel<<<(NEDGES + 255) / 256, 256>>>(srcp, dstp, edge_type);
    agg_kernel<<<AGG_BLOCKS, 256>>>(emb);

    // s1: weight prep for both layers (overlaps CSR + agg)
    cudaStreamWaitEvent(s1, e0, 0);
    wcat_kernel<<<KTOT, HID, 0, s1>>>(bases, coeffs, selfw, 0);
    wsplit_kernel<<<wsgrid, wsblk, 0, s1>>>(0);
    cudaEventRecord(e1, s1);
    wcat_kernel<<<KTOT, HID, 0, s1>>>(bases, coeffs, selfw, 1);
    wsplit_kernel<<<wsgrid, wsblk, 0, s1>>>(1);
    cudaEventRecord(e2, s1);

    // layer 0 GEMM
    cudaStreamWaitEvent(0, e1, 0);
    mma_gemm_kernel<<<ggrid, 512, GEMM_SMEM>>>(ahi_p, alo_p, bh_p, x1_p, NNODES, 1);

    // layer 1
    agg_kernel<<<AGG_BLOCKS, 256>>>(x1_p);
    cudaStreamWaitEvent(0, e2, 0);
    mma_gemm_kernel<<<ggrid, 512, GEMM_SMEM>>>(ahi_p, alo_p,
                                               bh_p + (size_t)HID * KTOT, outp, NNODES, 0);

    (void)out_size;
}

// round 12
// speedup vs baseline: 2.0115x; 1.4994x over previous
#include <cuda_runtime.h>
#include <cuda_fp16.h>
#include <cstdint>

// ---------------- problem constants ----------------
#define NNODES 50000
#define NEDGES 800000
#define NREL   8
#define HID    256
#define NBASES 30
#define KTOT   2304            // 8*256 relation cols + 256 self cols
#define MPAD   50176           // array padding; GEMM uses 391*128 = 50048 rows

// ---------------- device scratch (static, .bss zero-initialized) ----------------
__device__ int   g_deg8[NNODES * NREL];              // per-(node,rel) counts
__device__ float g_deginv[NNODES];
__device__ int   g_rowptr8[NNODES * NREL + 8];       // per-(node,rel) CSR offsets
__device__ int   g_cursor8[NNODES * NREL];
__device__ int   g_edges[NEDGES];                    // src only (sorted by node,rel)
__device__ __align__(256) __half g_Ah[(size_t)MPAD * KTOT];   // fp16 A; pad rows stay 0
__device__ float g_W[KTOT * HID];                    // W[k][o] fp32 (serial on s1)
__device__ __align__(256) __half g_Bh[2][HID * KTOT];  // per-layer W^T fp16: [o][k]
__device__ float g_x1[(size_t)MPAD * HID];

// ================= helpers =================
__device__ __forceinline__ uint32_t smem_to_u32(const void* p) {
    uint32_t a;
    asm("{ .reg .u64 t; cvta.to.shared.u64 t, %1; cvt.u32.u64 %0, t; }" : "=r"(a) : "l"(p));
    return a;
}
#define SWZ128(off) ((off) ^ (((off) >> 3) & 0x70))

__device__ __forceinline__ void cp16(uint32_t dst, const void* src) {
    asm volatile("cp.async.cg.shared.global [%0], [%1], 16;" :: "r"(dst), "l"(src));
}
__device__ __forceinline__ void ldsm4(uint32_t& r0, uint32_t& r1, uint32_t& r2, uint32_t& r3,
                                      uint32_t addr) {
    asm volatile("ldmatrix.sync.aligned.m8n8.x4.shared.b16 {%0,%1,%2,%3}, [%4];"
                 : "=r"(r0), "=r"(r1), "=r"(r2), "=r"(r3) : "r"(addr));
}
__device__ __forceinline__ void mma16816(float* c, const uint32_t* a, const uint32_t* b) {
    asm volatile("mma.sync.aligned.m16n8k16.row.col.f32.f16.f16.f32 "
                 "{%0,%1,%2,%3}, {%4,%5,%6,%7}, {%8,%9}, {%0,%1,%2,%3};"
                 : "+f"(c[0]), "+f"(c[1]), "+f"(c[2]), "+f"(c[3])
                 : "r"(a[0]), "r"(a[1]), "r"(a[2]), "r"(a[3]), "r"(b[0]), "r"(b[1]));
}

// ---------------- setup kernels ----------------
__global__ void hist_kernel(const int* __restrict__ dst, const int* __restrict__ rel) {
    int e = blockIdx.x * blockDim.x + threadIdx.x;
    if (e < NEDGES) atomicAdd(&g_deg8[dst[e] * NREL + rel[e]], 1);
}

// single-block shuffle scan over node degrees; also emits per-(node,rel) offsets
__global__ void scan_kernel() {
    __shared__ int wsum[32];
    int tid = threadIdx.x;
    int lane = tid & 31;
    int wid = tid >> 5;
    int carry = 0;
    for (int base = 0; base < NNODES; base += 1024) {
        int i = base + tid;
        int d8[8];
        int v = 0;
        if (i < NNODES) {
            int4 p0 = *reinterpret_cast<const int4*>(&g_deg8[i * 8]);
            int4 p1 = *reinterpret_cast<const int4*>(&g_deg8[i * 8 + 4]);
            d8[0] = p0.x; d8[1] = p0.y; d8[2] = p0.z; d8[3] = p0.w;
            d8[4] = p1.x; d8[5] = p1.y; d8[6] = p1.z; d8[7] = p1.w;
            v = d8[0] + d8[1] + d8[2] + d8[3] + d8[4] + d8[5] + d8[6] + d8[7];
        }
        int x = v;
        #pragma unroll
        for (int off = 1; off < 32; off <<= 1) {
            int t = __shfl_up_sync(0xFFFFFFFF, x, off);
            if (lane >= off) x += t;
        }
        if (lane == 31) wsum[wid] = x;
        __syncthreads();
        if (wid == 0) {
            int s = wsum[lane];
            #pragma unroll
            for (int off = 1; off < 32; off <<= 1) {
                int t = __shfl_up_sync(0xFFFFFFFF, s, off);
                if (lane >= off) s += t;
            }
            wsum[lane] = s;
        }
        __syncthreads();
        int excl = x - v + (wid > 0 ? wsum[wid - 1] : 0);
        int total = wsum[31];
        if (i < NNODES) {
            int off = carry + excl;
            int rp[8];
            #pragma unroll
            for (int r = 0; r < 8; r++) { rp[r] = off; off += d8[r]; }
            *reinterpret_cast<int4*>(&g_rowptr8[i * 8])     = make_int4(rp[0], rp[1], rp[2], rp[3]);
            *reinterpret_cast<int4*>(&g_rowptr8[i * 8 + 4]) = make_int4(rp[4], rp[5], rp[6], rp[7]);
            *reinterpret_cast<int4*>(&g_cursor8[i * 8])     = make_int4(rp[0], rp[1], rp[2], rp[3]);
            *reinterpret_cast<int4*>(&g_cursor8[i * 8 + 4]) = make_int4(rp[4], rp[5], rp[6], rp[7]);
            g_deginv[i] = 1.0f / fmaxf((float)v, 1.0f);
        }
        carry += total;
        __syncthreads();
    }
    if (tid == 0) g_rowptr8[NNODES * 8] = carry;     // == NEDGES
}

__global__ void scatter_kernel(const int* __restrict__ src,
                               const int* __restrict__ dst,
                               const int* __restrict__ rel) {
    int e = blockIdx.x * blockDim.x + threadIdx.x;
    if (e < NEDGES) {
        int pos = atomicAdd(&g_cursor8[dst[e] * NREL + rel[e]], 1);
        g_edges[pos] = src[e];
    }
}

// ---------------- weight assembly: g_W[k][o] fp32 ----------------
__global__ void wcat_kernel(const float* __restrict__ bases,
                            const float* __restrict__ coeffs,
                            const float* __restrict__ selfw,
                            int l) {
    int k = blockIdx.x;
    int o = threadIdx.x;
    if (k < 2048) {
        int r = k >> 8;
        int i = k & 255;
        const float* cf = coeffs + (l * NREL + r) * NBASES;
        const float* bs = bases + ((size_t)l * NBASES) * HID * HID + i * HID + o;
        float s = 0.f;
        #pragma unroll 6
        for (int b = 0; b < NBASES; b++)
            s += cf[b] * bs[(size_t)b * HID * HID];
        g_W[k * HID + o] = s;
    } else {
        g_W[k * HID + o] = selfw[(size_t)l * HID * HID + (k - 2048) * HID + o];
    }
}

// transpose + fp16 convert into per-layer buffer (B single fp16)
__global__ void wsplit_kernel(int l) {
    __shared__ float t[32][33];
    int k0 = blockIdx.x * 32, o0 = blockIdx.y * 32;
    int tx = threadIdx.x, ty = threadIdx.y;
    t[ty][tx] = g_W[(k0 + ty) * HID + o0 + tx];
    __syncthreads();
    float v = t[tx][ty];
    g_Bh[l][(size_t)(o0 + ty) * KTOT + k0 + tx] = __float2half_rn(v);
}

// ---------------- vectorized aggregation (rel-sorted CSR) -> fp16 A rows --------
// 64 threads/node, one accumulator, 8 sequential segments.
__device__ __forceinline__ uint32_t pack2h(float a, float b) {
    __half2 h = __halves2half2(__float2half_rn(a), __float2half_rn(b));
    return *reinterpret_cast<uint32_t*>(&h);
}
__device__ __forceinline__ void emit4(float4 v, __half* dst) {
    uint2 h;
    h.x = pack2h(v.x, v.y);
    h.y = pack2h(v.z, v.w);
    *reinterpret_cast<uint2*>(dst) = h;
}

__global__ __launch_bounds__(256) void agg_kernel(const float* __restrict__ xin) {
    int node = (blockIdx.x << 2) + (threadIdx.x >> 6);
    if (node >= NNODES) return;
    int c4 = threadIdx.x & 63;                 // float4 column index
    const float4* x4 = reinterpret_cast<const float4*>(xin);
    float dinv = g_deginv[node];
    size_t base = (size_t)node * KTOT + (c4 << 2);

    int j0 = g_rowptr8[node * 8];
    #pragma unroll 1
    for (int r = 0; r < 8; r++) {
        int j1 = g_rowptr8[node * 8 + r + 1];
        float4 a = make_float4(0.f, 0.f, 0.f, 0.f);
        #pragma unroll 2
        for (int j = j0; j < j1; j++) {
            int s = __ldg(&g_edges[j]);
            float4 v = __ldg(&x4[(size_t)s * 64 + c4]);
            a.x += v.x; a.y += v.y; a.z += v.z; a.w += v.w;
        }
        a.x *= dinv; a.y *= dinv; a.z *= dinv; a.w *= dinv;
        emit4(a, g_Ah + base + r * HID);
        j0 = j1;
    }
    float4 self = __ldg(&x4[(size_t)node * 64 + c4]);
    emit4(self, g_Ah + base + 2048);
}

// ---------------- HMMA GEMM: C[M,256] = A@Bh^T (single-pass fp16) ----------------
#define KC 64
#define NCHUNK (KTOT / KC)     // 36
#define ST_AH 0
#define ST_BH (16 * 1024)
#define STAGE_BYTES (48 * 1024)
#define GEMM_SMEM (2 * STAGE_BYTES)

__device__ __forceinline__ void load_chunk512(uint32_t sb, int brow, int k0, int tid,
                                              const __half* Ah, const __half* Bh) {
    // A: 1024 16B-units (128 rows x 8 chunks); B: 2048 units (256 rows x 8). 6/thread.
    #pragma unroll
    for (int it = 0; it < 6; it++) {
        int u = tid + it * 512;
        if (u < 1024) {
            int r = u >> 3, c = u & 7;
            uint32_t so = SWZ128((uint32_t)(r * 128 + c * 16));
            cp16(sb + ST_AH + so, Ah + (size_t)(brow + r) * KTOT + k0 + c * 8);
        } else {
            int idx = u - 1024;                 // 0..2047
            int r = idx >> 3, c = idx & 7;
            uint32_t so = SWZ128((uint32_t)(r * 128 + c * 16));
            cp16(sb + ST_BH + so, Bh + (size_t)r * KTOT + k0 + c * 8);
        }
    }
}

__global__ __launch_bounds__(512, 1) void mma_gemm_kernel(
    const __half* __restrict__ Ah, const __half* __restrict__ Bh,
    float* __restrict__ C, int m_store, int do_relu)
{
    extern __shared__ char smraw[];
    uint32_t smem_base = smem_to_u32(smraw);
    int tid = threadIdx.x;
    int wid = tid >> 5;
    int lane = tid & 31;
    int wm = wid & 3;
    int wn = wid >> 2;
    int brow = blockIdx.x * 128;

    float acc[2][8][4];
    #pragma unroll
    for (int i = 0; i < 2; i++)
        #pragma unroll
        for (int j = 0; j < 8; j++)
            #pragma unroll
            for (int q = 0; q < 4; q++) acc[i][j][q] = 0.f;

    load_chunk512(smem_base, brow, 0, tid, Ah, Bh);
    asm volatile("cp.async.commit_group;" ::: "memory");
    load_chunk512(smem_base + STAGE_BYTES, brow, KC, tid, Ah, Bh);
    asm volatile("cp.async.commit_group;" ::: "memory");

    int a_row = wm * 32 + (lane & 15);
    int a_kc8 = (lane >> 4) << 3;
    int tg = lane >> 3;
    int b_nbase = wn * 64 + ((tg >> 1) << 3) + (lane & 7);
    int b_kc8 = (tg & 1) << 3;

    for (int i = 0; i < NCHUNK; i++) {
        uint32_t sb = smem_base + (uint32_t)(i & 1) * STAGE_BYTES;
        asm volatile("cp.async.wait_group 1;" ::: "memory");
        __syncthreads();

        #pragma unroll
        for (int ks = 0; ks < 4; ks++) {
            int k = ks * 16;
            uint32_t ah[2][4], bh[4][4];
            #pragma unroll
            for (int g = 0; g < 2; g++) {
                uint32_t bo = (uint32_t)((a_row + g * 16) * 128 + (k + a_kc8) * 2);
                ldsm4(ah[g][0], ah[g][1], ah[g][2], ah[g][3], sb + ST_AH + SWZ128(bo));
            }
            #pragma unroll
            for (int j = 0; j < 4; j++) {
                uint32_t bo = (uint32_t)((b_nbase + j * 16) * 128 + (k + b_kc8) * 2);
                ldsm4(bh[j][0], bh[j][1], bh[j][2], bh[j][3], sb + ST_BH + SWZ128(bo));
            }
            #pragma unroll
            for (int mt = 0; mt < 2; mt++)
                #pragma unroll
                for (int nt = 0; nt < 8; nt++)
                    mma16816(acc[mt][nt], ah[mt], &bh[nt >> 1][(nt & 1) * 2]);
        }
        __syncthreads();
        if (i + 2 < NCHUNK)
            load_chunk512(sb, brow, (i + 2) * KC, tid, Ah, Bh);
        asm volatile("cp.async.commit_group;" ::: "memory");
    }

    int col = wn * 64 + 2 * (lane & 3);
    #pragma unroll
    for (int mt = 0; mt < 2; mt++) {
        int r0 = brow + wm * 32 + mt * 16 + (lane >> 2);
        int r1 = r0 + 8;
        #pragma unroll
        for (int nt = 0; nt < 8; nt++) {
            float2 v0 = make_float2(acc[mt][nt][0], acc[mt][nt][1]);
            float2 v1 = make_float2(acc[mt][nt][2], acc[mt][nt][3]);
            if (do_relu) {
                v0.x = fmaxf(v0.x, 0.f); v0.y = fmaxf(v0.y, 0.f);
                v1.x = fmaxf(v1.x, 0.f); v1.y = fmaxf(v1.y, 0.f);
            }
            if (r0 < m_store)
                *reinterpret_cast<float2*>(&C[(size_t)r0 * HID + col + nt * 8]) = v0;
            if (r1 < m_store)
                *reinterpret_cast<float2*>(&C[(size_t)r1 * HID + col + nt * 8]) = v1;
        }
    }
}

// ---------------- launch ----------------
extern "C" void kernel_launch(void* const* d_in, const int* in_sizes, int n_in,
                              void* d_out, int out_size) {
    const int*   edge_index = nullptr;
    const int*   edge_type  = nullptr;
    const float* emb        = nullptr;
    const float* bases      = nullptr;
    const float* coeffs     = nullptr;
    const float* selfw      = nullptr;
    for (int i = 0; i < n_in; i++) {
        switch (in_sizes[i]) {
            case 2 * NEDGES:             edge_index = (const int*)d_in[i]; break;
            case NEDGES:                 edge_type  = (const int*)d_in[i]; break;
            case NNODES * HID:           emb        = (const float*)d_in[i]; break;
            case 2 * NBASES * HID * HID: bases      = (const float*)d_in[i]; break;
            case 2 * NREL * NBASES:      coeffs     = (const float*)d_in[i]; break;
            case 2 * HID * HID:          selfw      = (const float*)d_in[i]; break;
            default: break;
        }
    }
    const int* srcp = edge_index;
    const int* dstp = edge_index + NEDGES;
    float* outp = (float*)d_out;

    static cudaStream_t s1 = nullptr;
    static cudaEvent_t e0, e1, e2;
    if (!s1) {
        cudaStreamCreateWithFlags(&s1, cudaStreamNonBlocking);
        cudaEventCreateWithFlags(&e0, cudaEventDisableTiming);
        cudaEventCreateWithFlags(&e1, cudaEventDisableTiming);
        cudaEventCreateWithFlags(&e2, cudaEventDisableTiming);
    }

    int* deg8_p;
    __half *ah_p, *bh_p;
    float* x1_p;
    cudaGetSymbolAddress((void**)&deg8_p, g_deg8);
    cudaGetSymbolAddress((void**)&ah_p, g_Ah);
    cudaGetSymbolAddress((void**)&bh_p, g_Bh);
    cudaGetSymbolAddress((void**)&x1_p, g_x1);

    cudaFuncSetAttribute(mma_gemm_kernel, cudaFuncAttributeMaxDynamicSharedMemorySize, GEMM_SMEM);

    dim3 wsgrid(KTOT / 32, HID / 32);
    dim3 wsblk(32, 32);
    const int AGG_BLOCKS = (NNODES + 3) / 4;     // 12500
    int ggrid = 391;

    cudaEventRecord(e0, 0);

    // stream0: CSR build (rel-sorted) + agg0
    cudaMemsetAsync(deg8_p, 0, NNODES * NREL * sizeof(int), 0);
    hist_kernel<<<(NEDGES + 255) / 256, 256>>>(dstp, edge_type);
    scan_kernel<<<1, 1024>>>();
    scatter_kernel<<<(NEDGES + 255) / 256, 256>>>(srcp, dstp, edge_type);
    agg_kernel<<<AGG_BLOCKS, 256>>>(emb);

    // s1: weight prep for both layers (overlaps CSR + agg)
    cudaStreamWaitEvent(s1, e0, 0);
    wcat_kernel<<<KTOT, HID, 0, s1>>>(bases, coeffs, selfw, 0);
    wsplit_kernel<<<wsgrid, wsblk, 0, s1>>>(0);
    cudaEventRecord(e1, s1);
    wcat_kernel<<<KTOT, HID, 0, s1>>>(bases, coeffs, selfw, 1);
    wsplit_kernel<<<wsgrid, wsblk, 0, s1>>>(1);
    cudaEventRecord(e2, s1);

    // layer 0 GEMM
    cudaStreamWaitEvent(0, e1, 0);
    mma_gemm_kernel<<<ggrid, 512, GEMM_SMEM>>>(ah_p, bh_p, x1_p, NNODES, 1);

    // layer 1
    agg_kernel<<<AGG_BLOCKS, 256>>>(x1_p);
    cudaStreamWaitEvent(0, e2, 0);
    mma_gemm_kernel<<<ggrid, 512, GEMM_SMEM>>>(ah_p, bh_p + (size_t)HID * KTOT,
                                               outp, NNODES, 0);

    (void)out_size;
}

// round 13
// speedup vs baseline: 2.0880x; 1.0380x over previous
#include <cuda_runtime.h>
#include <cuda_fp16.h>
#include <cstdint>

// ---------------- problem constants ----------------
#define NNODES 50000
#define NEDGES 800000
#define NREL   8
#define HID    256
#define NBASES 30
#define KTOT   2304            // 8*256 relation cols + 256 self cols
#define MPAD   50176           // array padding; GEMM uses 391*128 = 50048 rows

// ---------------- device scratch (static, .bss zero-initialized) ----------------
__device__ int   g_deg8[NNODES * NREL];              // per-(node,rel) counts
__device__ float g_deginv[NNODES];
__device__ int   g_rowptr8[NNODES * NREL + 8];       // per-(node,rel) CSR offsets
__device__ int   g_cursor8[NNODES * NREL];
__device__ int   g_edges[NEDGES];                    // src only (sorted by node,rel)
__device__ __align__(256) __half g_Ah[(size_t)MPAD * KTOT];   // fp16 A; pad rows stay 0
__device__ float g_W[KTOT * HID];                    // W[k][o] fp32 (serial on s1)
__device__ __align__(256) __half g_Bh[2][HID * KTOT];  // per-layer W^T fp16: [o][k]
__device__ float g_x1[(size_t)MPAD * HID];

// ================= helpers =================
__device__ __forceinline__ uint32_t smem_to_u32(const void* p) {
    uint32_t a;
    asm("{ .reg .u64 t; cvta.to.shared.u64 t, %1; cvt.u32.u64 %0, t; }" : "=r"(a) : "l"(p));
    return a;
}
#define SWZ128(off) ((off) ^ (((off) >> 3) & 0x70))

__device__ __forceinline__ void cp16(uint32_t dst, const void* src) {
    asm volatile("cp.async.cg.shared.global [%0], [%1], 16;" :: "r"(dst), "l"(src));
}
__device__ __forceinline__ void ldsm4(uint32_t& r0, uint32_t& r1, uint32_t& r2, uint32_t& r3,
                                      uint32_t addr) {
    asm volatile("ldmatrix.sync.aligned.m8n8.x4.shared.b16 {%0,%1,%2,%3}, [%4];"
                 : "=r"(r0), "=r"(r1), "=r"(r2), "=r"(r3) : "r"(addr));
}
__device__ __forceinline__ void mma16816(float* c, const uint32_t* a, const uint32_t* b) {
    asm volatile("mma.sync.aligned.m16n8k16.row.col.f32.f16.f16.f32 "
                 "{%0,%1,%2,%3}, {%4,%5,%6,%7}, {%8,%9}, {%0,%1,%2,%3};"
                 : "+f"(c[0]), "+f"(c[1]), "+f"(c[2]), "+f"(c[3])
                 : "r"(a[0]), "r"(a[1]), "r"(a[2]), "r"(a[3]), "r"(b[0]), "r"(b[1]));
}

// ---------------- setup kernels ----------------
__global__ void hist_kernel(const int* __restrict__ dst, const int* __restrict__ rel) {
    int e = blockIdx.x * blockDim.x + threadIdx.x;
    if (e < NEDGES) atomicAdd(&g_deg8[dst[e] * NREL + rel[e]], 1);
}

// single-block shuffle scan over node degrees; also emits per-(node,rel) offsets
__global__ void scan_kernel() {
    __shared__ int wsum[32];
    int tid = threadIdx.x;
    int lane = tid & 31;
    int wid = tid >> 5;
    int carry = 0;
    for (int base = 0; base < NNODES; base += 1024) {
        int i = base + tid;
        int d8[8];
        int v = 0;
        if (i < NNODES) {
            int4 p0 = *reinterpret_cast<const int4*>(&g_deg8[i * 8]);
            int4 p1 = *reinterpret_cast<const int4*>(&g_deg8[i * 8 + 4]);
            d8[0] = p0.x; d8[1] = p0.y; d8[2] = p0.z; d8[3] = p0.w;
            d8[4] = p1.x; d8[5] = p1.y; d8[6] = p1.z; d8[7] = p1.w;
            v = d8[0] + d8[1] + d8[2] + d8[3] + d8[4] + d8[5] + d8[6] + d8[7];
        }
        int x = v;
        #pragma unroll
        for (int off = 1; off < 32; off <<= 1) {
            int t = __shfl_up_sync(0xFFFFFFFF, x, off);
            if (lane >= off) x += t;
        }
        if (lane == 31) wsum[wid] = x;
        __syncthreads();
        if (wid == 0) {
            int s = wsum[lane];
            #pragma unroll
            for (int off = 1; off < 32; off <<= 1) {
                int t = __shfl_up_sync(0xFFFFFFFF, s, off);
                if (lane >= off) s += t;
            }
            wsum[lane] = s;
        }
        __syncthreads();
        int excl = x - v + (wid > 0 ? wsum[wid - 1] : 0);
        int total = wsum[31];
        if (i < NNODES) {
            int off = carry + excl;
            int rp[8];
            #pragma unroll
            for (int r = 0; r < 8; r++) { rp[r] = off; off += d8[r]; }
            *reinterpret_cast<int4*>(&g_rowptr8[i * 8])     = make_int4(rp[0], rp[1], rp[2], rp[3]);
            *reinterpret_cast<int4*>(&g_rowptr8[i * 8 + 4]) = make_int4(rp[4], rp[5], rp[6], rp[7]);
            *reinterpret_cast<int4*>(&g_cursor8[i * 8])     = make_int4(rp[0], rp[1], rp[2], rp[3]);
            *reinterpret_cast<int4*>(&g_cursor8[i * 8 + 4]) = make_int4(rp[4], rp[5], rp[6], rp[7]);
            g_deginv[i] = 1.0f / fmaxf((float)v, 1.0f);
        }
        carry += total;
        __syncthreads();
    }
    if (tid == 0) g_rowptr8[NNODES * 8] = carry;     // == NEDGES
}

__global__ void scatter_kernel(const int* __restrict__ src,
                               const int* __restrict__ dst,
                               const int* __restrict__ rel) {
    int e = blockIdx.x * blockDim.x + threadIdx.x;
    if (e < NEDGES) {
        int pos = atomicAdd(&g_cursor8[dst[e] * NREL + rel[e]], 1);
        g_edges[pos] = src[e];
    }
}

// ---------------- weight assembly: g_W[k][o] fp32 ----------------
__global__ void wcat_kernel(const float* __restrict__ bases,
                            const float* __restrict__ coeffs,
                            const float* __restrict__ selfw,
                            int l) {
    int k = blockIdx.x;
    int o = threadIdx.x;
    if (k < 2048) {
        int r = k >> 8;
        int i = k & 255;
        const float* cf = coeffs + (l * NREL + r) * NBASES;
        const float* bs = bases + ((size_t)l * NBASES) * HID * HID + i * HID + o;
        float s = 0.f;
        #pragma unroll 6
        for (int b = 0; b < NBASES; b++)
            s += cf[b] * bs[(size_t)b * HID * HID];
        g_W[k * HID + o] = s;
    } else {
        g_W[k * HID + o] = selfw[(size_t)l * HID * HID + (k - 2048) * HID + o];
    }
}

// transpose + fp16 convert into per-layer buffer (B single fp16)
__global__ void wsplit_kernel(int l) {
    __shared__ float t[32][33];
    int k0 = blockIdx.x * 32, o0 = blockIdx.y * 32;
    int tx = threadIdx.x, ty = threadIdx.y;
    t[ty][tx] = g_W[(k0 + ty) * HID + o0 + tx];
    __syncthreads();
    float v = t[tx][ty];
    g_Bh[l][(size_t)(o0 + ty) * KTOT + k0 + tx] = __float2half_rn(v);
}

// ---------------- vectorized aggregation (rel-sorted CSR) -> fp16 A rows --------
// 64 threads/node, one accumulator, 8 sequential segments.
__device__ __forceinline__ uint32_t pack2h(float a, float b) {
    __half2 h = __halves2half2(__float2half_rn(a), __float2half_rn(b));
    return *reinterpret_cast<uint32_t*>(&h);
}
__device__ __forceinline__ void emit4(float4 v, __half* dst) {
    uint2 h;
    h.x = pack2h(v.x, v.y);
    h.y = pack2h(v.z, v.w);
    *reinterpret_cast<uint2*>(dst) = h;
}

__global__ __launch_bounds__(256) void agg_kernel(const float* __restrict__ xin) {
    int node = (blockIdx.x << 2) + (threadIdx.x >> 6);
    if (node >= NNODES) return;
    int c4 = threadIdx.x & 63;                 // float4 column index
    const float4* x4 = reinterpret_cast<const float4*>(xin);
    float dinv = g_deginv[node];
    size_t base = (size_t)node * KTOT + (c4 << 2);

    int j0 = g_rowptr8[node * 8];
    #pragma unroll 1
    for (int r = 0; r < 8; r++) {
        int j1 = g_rowptr8[node * 8 + r + 1];
        float4 a = make_float4(0.f, 0.f, 0.f, 0.f);
        #pragma unroll 2
        for (int j = j0; j < j1; j++) {
            int s = __ldg(&g_edges[j]);
            float4 v = __ldg(&x4[(size_t)s * 64 + c4]);
            a.x += v.x; a.y += v.y; a.z += v.z; a.w += v.w;
        }
        a.x *= dinv; a.y *= dinv; a.z *= dinv; a.w *= dinv;
        emit4(a, g_Ah + base + r * HID);
        j0 = j1;
    }
    float4 self = __ldg(&x4[(size_t)node * 64 + c4]);
    emit4(self, g_Ah + base + 2048);
}

// ---------------- HMMA GEMM: C[M,256] = A@Bh^T (1-pass fp16, 4-stage pipeline) ------
#define KC 64
#define NCHUNK (KTOT / KC)     // 36
#define NSTAGE 4
#define ST_AH 0
#define ST_BH (16 * 1024)
#define STAGE_BYTES (48 * 1024)
#define GEMM_SMEM (NSTAGE * STAGE_BYTES)

__device__ __forceinline__ void load_chunk512(uint32_t sb, int brow, int k0, int tid,
                                              const __half* Ah, const __half* Bh) {
    // A: 1024 16B-units (128 rows x 8 chunks); B: 2048 units (256 rows x 8). 6/thread.
    #pragma unroll
    for (int it = 0; it < 6; it++) {
        int u = tid + it * 512;
        if (u < 1024) {
            int r = u >> 3, c = u & 7;
            uint32_t so = SWZ128((uint32_t)(r * 128 + c * 16));
            cp16(sb + ST_AH + so, Ah + (size_t)(brow + r) * KTOT + k0 + c * 8);
        } else {
            int idx = u - 1024;                 // 0..2047
            int r = idx >> 3, c = idx & 7;
            uint32_t so = SWZ128((uint32_t)(r * 128 + c * 16));
            cp16(sb + ST_BH + so, Bh + (size_t)r * KTOT + k0 + c * 8);
        }
    }
}

__global__ __launch_bounds__(512, 1) void mma_gemm_kernel(
    const __half* __restrict__ Ah, const __half* __restrict__ Bh,
    float* __restrict__ C, int m_store, int do_relu)
{
    extern __shared__ char smraw[];
    uint32_t smem_base = smem_to_u32(smraw);
    int tid = threadIdx.x;
    int wid = tid >> 5;
    int lane = tid & 31;
    int wm = wid & 3;
    int wn = wid >> 2;
    int brow = blockIdx.x * 128;

    float acc[2][8][4];
    #pragma unroll
    for (int i = 0; i < 2; i++)
        #pragma unroll
        for (int j = 0; j < 8; j++)
            #pragma unroll
            for (int q = 0; q < 4; q++) acc[i][j][q] = 0.f;

    // prologue: fill 3 stages
    #pragma unroll
    for (int p = 0; p < NSTAGE - 1; p++) {
        load_chunk512(smem_base + (uint32_t)p * STAGE_BYTES, brow, p * KC, tid, Ah, Bh);
        asm volatile("cp.async.commit_group;" ::: "memory");
    }

    int a_row = wm * 32 + (lane & 15);
    int a_kc8 = (lane >> 4) << 3;
    int tg = lane >> 3;
    int b_nbase = wn * 64 + ((tg >> 1) << 3) + (lane & 7);
    int b_kc8 = (tg & 1) << 3;

    for (int i = 0; i < NCHUNK; i++) {
        uint32_t sb = smem_base + (uint32_t)(i & (NSTAGE - 1)) * STAGE_BYTES;
        asm volatile("cp.async.wait_group %0;" :: "n"(NSTAGE - 2) : "memory");
        __syncthreads();

        #pragma unroll
        for (int ks = 0; ks < 4; ks++) {
            int k = ks * 16;
            uint32_t ah[2][4], bh[4][4];
            #pragma unroll
            for (int g = 0; g < 2; g++) {
                uint32_t bo = (uint32_t)((a_row + g * 16) * 128 + (k + a_kc8) * 2);
                ldsm4(ah[g][0], ah[g][1], ah[g][2], ah[g][3], sb + ST_AH + SWZ128(bo));
            }
            #pragma unroll
            for (int j = 0; j < 4; j++) {
                uint32_t bo = (uint32_t)((b_nbase + j * 16) * 128 + (k + b_kc8) * 2);
                ldsm4(bh[j][0], bh[j][1], bh[j][2], bh[j][3], sb + ST_BH + SWZ128(bo));
            }
            #pragma unroll
            for (int mt = 0; mt < 2; mt++)
                #pragma unroll
                for (int nt = 0; nt < 8; nt++)
                    mma16816(acc[mt][nt], ah[mt], &bh[nt >> 1][(nt & 1) * 2]);
        }
        // refill stage (i + NSTAGE - 1) — it was last READ in iter i-1, which every
        // warp finished before passing this iter's barrier.
        int j = i + NSTAGE - 1;
        if (j < NCHUNK) {
            uint32_t wb = smem_base + (uint32_t)(j & (NSTAGE - 1)) * STAGE_BYTES;
            load_chunk512(wb, brow, j * KC, tid, Ah, Bh);
        }
        asm volatile("cp.async.commit_group;" ::: "memory");
    }

    int col = wn * 64 + 2 * (lane & 3);
    #pragma unroll
    for (int mt = 0; mt < 2; mt++) {
        int r0 = brow + wm * 32 + mt * 16 + (lane >> 2);
        int r1 = r0 + 8;
        #pragma unroll
        for (int nt = 0; nt < 8; nt++) {
            float2 v0 = make_float2(acc[mt][nt][0], acc[mt][nt][1]);
            float2 v1 = make_float2(acc[mt][nt][2], acc[mt][nt][3]);
            if (do_relu) {
                v0.x = fmaxf(v0.x, 0.f); v0.y = fmaxf(v0.y, 0.f);
                v1.x = fmaxf(v1.x, 0.f); v1.y = fmaxf(v1.y, 0.f);
            }
            if (r0 < m_store)
                *reinterpret_cast<float2*>(&C[(size_t)r0 * HID + col + nt * 8]) = v0;
            if (r1 < m_store)
                *reinterpret_cast<float2*>(&C[(size_t)r1 * HID + col + nt * 8]) = v1;
        }
    }
}

// ---------------- launch ----------------
extern "C" void kernel_launch(void* const* d_in, const int* in_sizes, int n_in,
                              void* d_out, int out_size) {
    const int*   edge_index = nullptr;
    const int*   edge_type  = nullptr;
    const float* emb        = nullptr;
    const float* bases      = nullptr;
    const float* coeffs     = nullptr;
    const float* selfw      = nullptr;
    for (int i = 0; i < n_in; i++) {
        switch (in_sizes[i]) {
            case 2 * NEDGES:             edge_index = (const int*)d_in[i]; break;
            case NEDGES:                 edge_type  = (const int*)d_in[i]; break;
            case NNODES * HID:           emb        = (const float*)d_in[i]; break;
            case 2 * NBASES * HID * HID: bases      = (const float*)d_in[i]; break;
            case 2 * NREL * NBASES:      coeffs     = (const float*)d_in[i]; break;
            case 2 * HID * HID:          selfw      = (const float*)d_in[i]; break;
            default: break;
        }
    }
    const int* srcp = edge_index;
    const int* dstp = edge_index + NEDGES;
    float* outp = (float*)d_out;

    static cudaStream_t s1 = nullptr;
    static cudaEvent_t e0, e1, e2;
    if (!s1) {
        cudaStreamCreateWithFlags(&s1, cudaStreamNonBlocking);
        cudaEventCreateWithFlags(&e0, cudaEventDisableTiming);
        cudaEventCreateWithFlags(&e1, cudaEventDisableTiming);
        cudaEventCreateWithFlags(&e2, cudaEventDisableTiming);
    }

    int* deg8_p;
    __half *ah_p, *bh_p;
    float* x1_p;
    cudaGetSymbolAddress((void**)&deg8_p, g_deg8);
    cudaGetSymbolAddress((void**)&ah_p, g_Ah);
    cudaGetSymbolAddress((void**)&bh_p, g_Bh);
    cudaGetSymbolAddress((void**)&x1_p, g_x1);

    cudaFuncSetAttribute(mma_gemm_kernel, cudaFuncAttributeMaxDynamicSharedMemorySize, GEMM_SMEM);

    dim3 wsgrid(KTOT / 32, HID / 32);
    dim3 wsblk(32, 32);
    const int AGG_BLOCKS = (NNODES + 3) / 4;     // 12500
    int ggrid = 391;

    cudaEventRecord(e0, 0);

    // stream0: CSR build (rel-sorted) + agg0
    cudaMemsetAsync(deg8_p, 0, NNODES * NREL * sizeof(int), 0);
    hist_kernel<<<(NEDGES + 255) / 256, 256>>>(dstp, edge_type);
    scan_kernel<<<1, 1024>>>();
    scatter_kernel<<<(NEDGES + 255) / 256, 256>>>(srcp, dstp, edge_type);
    agg_kernel<<<AGG_BLOCKS, 256>>>(emb);

    // s1: weight prep for both layers (overlaps CSR + agg)
    cudaStreamWaitEvent(s1, e0, 0);
    wcat_kernel<<<KTOT, HID, 0, s1>>>(bases, coeffs, selfw, 0);
    wsplit_kernel<<<wsgrid, wsblk, 0, s1>>>(0);
    cudaEventRecord(e1, s1);
    wcat_kernel<<<KTOT, HID, 0, s1>>>(bases, coeffs, selfw, 1);
    wsplit_kernel<<<wsgrid, wsblk, 0, s1>>>(1);
    cudaEventRecord(e2, s1);

    // layer 0 GEMM
    cudaStreamWaitEvent(0, e1, 0);
    mma_gemm_kernel<<<ggrid, 512, GEMM_SMEM>>>(ah_p, bh_p, x1_p, NNODES, 1);

    // layer 1
    agg_kernel<<<AGG_BLOCKS, 256>>>(x1_p);
    cudaStreamWaitEvent(0, e2, 0);
    mma_gemm_kernel<<<ggrid, 512, GEMM_SMEM>>>(ah_p, bh_p + (size_t)HID * KTOT,
                                               outp, NNODES, 0);

    (void)out_size;
}

// round 14
// speedup vs baseline: 2.0970x; 1.0043x over previous
#include <cuda_runtime.h>
#include <cuda_fp16.h>
#include <cstdint>

// ---------------- problem constants ----------------
#define NNODES 50000
#define NEDGES 800000
#define NREL   8
#define HID    256
#define NBASES 30
#define KTOT   2304            // 8*256 relation cols + 256 self cols
#define MPAD   50176           // array padding; GEMM uses 391*128 = 50048 rows

// ---------------- device scratch (static, .bss zero-initialized) ----------------
__device__ int   g_deg8[NNODES * NREL];              // per-(node,rel) counts
__device__ float g_deginv[NNODES];
__device__ int   g_rowptr8[NNODES * NREL + 8];       // per-(node,rel) CSR offsets
__device__ int   g_cursor8[NNODES * NREL];
__device__ int   g_edges[NEDGES];                    // src only (sorted by node,rel)
__device__ __align__(256) __half g_Ah[(size_t)MPAD * KTOT];   // fp16 A; pad rows stay 0
__device__ float g_W[KTOT * HID];                    // W[k][o] fp32 (serial on s1)
__device__ __align__(256) __half g_Bh[2][HID * KTOT];  // per-layer W^T fp16: [o][k]
__device__ __align__(256) __half g_x1h[(size_t)MPAD * HID];   // fp16 layer-0 output

// ================= helpers =================
__device__ __forceinline__ uint32_t smem_to_u32(const void* p) {
    uint32_t a;
    asm("{ .reg .u64 t; cvta.to.shared.u64 t, %1; cvt.u32.u64 %0, t; }" : "=r"(a) : "l"(p));
    return a;
}
#define SWZ128(off) ((off) ^ (((off) >> 3) & 0x70))

__device__ __forceinline__ void cp16(uint32_t dst, const void* src) {
    asm volatile("cp.async.cg.shared.global [%0], [%1], 16;" :: "r"(dst), "l"(src));
}
__device__ __forceinline__ void ldsm4(uint32_t& r0, uint32_t& r1, uint32_t& r2, uint32_t& r3,
                                      uint32_t addr) {
    asm volatile("ldmatrix.sync.aligned.m8n8.x4.shared.b16 {%0,%1,%2,%3}, [%4];"
                 : "=r"(r0), "=r"(r1), "=r"(r2), "=r"(r3) : "r"(addr));
}
__device__ __forceinline__ void mma16816(float* c, const uint32_t* a, const uint32_t* b) {
    asm volatile("mma.sync.aligned.m16n8k16.row.col.f32.f16.f16.f32 "
                 "{%0,%1,%2,%3}, {%4,%5,%6,%7}, {%8,%9}, {%0,%1,%2,%3};"
                 : "+f"(c[0]), "+f"(c[1]), "+f"(c[2]), "+f"(c[3])
                 : "r"(a[0]), "r"(a[1]), "r"(a[2]), "r"(a[3]), "r"(b[0]), "r"(b[1]));
}

// ---------------- setup kernels ----------------
__global__ void hist_kernel(const int* __restrict__ dst, const int* __restrict__ rel) {
    int e = blockIdx.x * blockDim.x + threadIdx.x;
    if (e < NEDGES) atomicAdd(&g_deg8[dst[e] * NREL + rel[e]], 1);
}

// single-block shuffle scan over node degrees; also emits per-(node,rel) offsets
__global__ void scan_kernel() {
    __shared__ int wsum[32];
    int tid = threadIdx.x;
    int lane = tid & 31;
    int wid = tid >> 5;
    int carry = 0;
    for (int base = 0; base < NNODES; base += 1024) {
        int i = base + tid;
        int d8[8];
        int v = 0;
        if (i < NNODES) {
            int4 p0 = *reinterpret_cast<const int4*>(&g_deg8[i * 8]);
            int4 p1 = *reinterpret_cast<const int4*>(&g_deg8[i * 8 + 4]);
            d8[0] = p0.x; d8[1] = p0.y; d8[2] = p0.z; d8[3] = p0.w;
            d8[4] = p1.x; d8[5] = p1.y; d8[6] = p1.z; d8[7] = p1.w;
            v = d8[0] + d8[1] + d8[2] + d8[3] + d8[4] + d8[5] + d8[6] + d8[7];
        }
        int x = v;
        #pragma unroll
        for (int off = 1; off < 32; off <<= 1) {
            int t = __shfl_up_sync(0xFFFFFFFF, x, off);
            if (lane >= off) x += t;
        }
        if (lane == 31) wsum[wid] = x;
        __syncthreads();
        if (wid == 0) {
            int s = wsum[lane];
            #pragma unroll
            for (int off = 1; off < 32; off <<= 1) {
                int t = __shfl_up_sync(0xFFFFFFFF, s, off);
                if (lane >= off) s += t;
            }
            wsum[lane] = s;
        }
        __syncthreads();
        int excl = x - v + (wid > 0 ? wsum[wid - 1] : 0);
        int total = wsum[31];
        if (i < NNODES) {
            int off = carry + excl;
            int rp[8];
            #pragma unroll
            for (int r = 0; r < 8; r++) { rp[r] = off; off += d8[r]; }
            *reinterpret_cast<int4*>(&g_rowptr8[i * 8])     = make_int4(rp[0], rp[1], rp[2], rp[3]);
            *reinterpret_cast<int4*>(&g_rowptr8[i * 8 + 4]) = make_int4(rp[4], rp[5], rp[6], rp[7]);
            *reinterpret_cast<int4*>(&g_cursor8[i * 8])     = make_int4(rp[0], rp[1], rp[2], rp[3]);
            *reinterpret_cast<int4*>(&g_cursor8[i * 8 + 4]) = make_int4(rp[4], rp[5], rp[6], rp[7]);
            g_deginv[i] = 1.0f / fmaxf((float)v, 1.0f);
        }
        carry += total;
        __syncthreads();
    }
    if (tid == 0) g_rowptr8[NNODES * 8] = carry;     // == NEDGES
}

__global__ void scatter_kernel(const int* __restrict__ src,
                               const int* __restrict__ dst,
                               const int* __restrict__ rel) {
    int e = blockIdx.x * blockDim.x + threadIdx.x;
    if (e < NEDGES) {
        int pos = atomicAdd(&g_cursor8[dst[e] * NREL + rel[e]], 1);
        g_edges[pos] = src[e];
    }
}

// ---------------- weight assembly: g_W[k][o] fp32 ----------------
__global__ void wcat_kernel(const float* __restrict__ bases,
                            const float* __restrict__ coeffs,
                            const float* __restrict__ selfw,
                            int l) {
    int k = blockIdx.x;
    int o = threadIdx.x;
    if (k < 2048) {
        int r = k >> 8;
        int i = k & 255;
        const float* cf = coeffs + (l * NREL + r) * NBASES;
        const float* bs = bases + ((size_t)l * NBASES) * HID * HID + i * HID + o;
        float s = 0.f;
        #pragma unroll 6
        for (int b = 0; b < NBASES; b++)
            s += cf[b] * bs[(size_t)b * HID * HID];
        g_W[k * HID + o] = s;
    } else {
        g_W[k * HID + o] = selfw[(size_t)l * HID * HID + (k - 2048) * HID + o];
    }
}

// transpose + fp16 convert into per-layer buffer (B single fp16)
__global__ void wsplit_kernel(int l) {
    __shared__ float t[32][33];
    int k0 = blockIdx.x * 32, o0 = blockIdx.y * 32;
    int tx = threadIdx.x, ty = threadIdx.y;
    t[ty][tx] = g_W[(k0 + ty) * HID + o0 + tx];
    __syncthreads();
    float v = t[tx][ty];
    g_Bh[l][(size_t)(o0 + ty) * KTOT + k0 + tx] = __float2half_rn(v);
}

// ---------------- vectorized aggregation (rel-sorted CSR) -> fp16 A rows --------
// 64 threads/node, one accumulator, 8 sequential segments. Templated on input type.
__device__ __forceinline__ uint32_t pack2h(float a, float b) {
    __half2 h = __halves2half2(__float2half_rn(a), __float2half_rn(b));
    return *reinterpret_cast<uint32_t*>(&h);
}
__device__ __forceinline__ void emit4(float4 v, __half* dst) {
    uint2 h;
    h.x = pack2h(v.x, v.y);
    h.y = pack2h(v.z, v.w);
    *reinterpret_cast<uint2*>(dst) = h;
}

template <bool HALF_IN>
__global__ __launch_bounds__(256) void agg_kernel(const void* __restrict__ xin) {
    int node = (blockIdx.x << 2) + (threadIdx.x >> 6);
    if (node >= NNODES) return;
    int c4 = threadIdx.x & 63;                 // 4-column group index
    const float4* x4 = reinterpret_cast<const float4*>(xin);
    const __half2* h2 = reinterpret_cast<const __half2*>(xin);
    float dinv = g_deginv[node];
    size_t base = (size_t)node * KTOT + (c4 << 2);

    int j0 = g_rowptr8[node * 8];
    #pragma unroll 1
    for (int r = 0; r < 8; r++) {
        int j1 = g_rowptr8[node * 8 + r + 1];
        float4 a = make_float4(0.f, 0.f, 0.f, 0.f);
        #pragma unroll 2
        for (int j = j0; j < j1; j++) {
            int s = __ldg(&g_edges[j]);
            float4 v;
            if (HALF_IN) {
                uint2 raw = __ldg(reinterpret_cast<const uint2*>(&h2[(size_t)s * 128 + c4 * 2]));
                __half2 ha = *reinterpret_cast<__half2*>(&raw.x);
                __half2 hb = *reinterpret_cast<__half2*>(&raw.y);
                float2 fa = __half22float2(ha);
                float2 fb = __half22float2(hb);
                v = make_float4(fa.x, fa.y, fb.x, fb.y);
            } else {
                v = __ldg(&x4[(size_t)s * 64 + c4]);
            }
            a.x += v.x; a.y += v.y; a.z += v.z; a.w += v.w;
        }
        a.x *= dinv; a.y *= dinv; a.z *= dinv; a.w *= dinv;
        emit4(a, g_Ah + base + r * HID);
        j0 = j1;
    }
    // self column
    float4 self;
    if (HALF_IN) {
        uint2 raw = __ldg(reinterpret_cast<const uint2*>(&h2[(size_t)node * 128 + c4 * 2]));
        __half2 ha = *reinterpret_cast<__half2*>(&raw.x);
        __half2 hb = *reinterpret_cast<__half2*>(&raw.y);
        float2 fa = __half22float2(ha);
        float2 fb = __half22float2(hb);
        self = make_float4(fa.x, fa.y, fb.x, fb.y);
    } else {
        self = __ldg(&x4[(size_t)node * 64 + c4]);
    }
    emit4(self, g_Ah + base + 2048);
}

// ---------------- HMMA GEMM: C = A@Bh^T (1-pass fp16, 4-stage pipeline) ------
// Output: fp32 to C when Ch == nullptr, else fp16 to Ch (layer-0 path).
#define KC 64
#define NCHUNK (KTOT / KC)     // 36
#define NSTAGE 4
#define ST_AH 0
#define ST_BH (16 * 1024)
#define STAGE_BYTES (48 * 1024)
#define GEMM_SMEM (NSTAGE * STAGE_BYTES)

__device__ __forceinline__ void load_chunk512(uint32_t sb, int brow, int k0, int tid,
                                              const __half* Ah, const __half* Bh) {
    #pragma unroll
    for (int it = 0; it < 6; it++) {
        int u = tid + it * 512;
        if (u < 1024) {
            int r = u >> 3, c = u & 7;
            uint32_t so = SWZ128((uint32_t)(r * 128 + c * 16));
            cp16(sb + ST_AH + so, Ah + (size_t)(brow + r) * KTOT + k0 + c * 8);
        } else {
            int idx = u - 1024;
            int r = idx >> 3, c = idx & 7;
            uint32_t so = SWZ128((uint32_t)(r * 128 + c * 16));
            cp16(sb + ST_BH + so, Bh + (size_t)r * KTOT + k0 + c * 8);
        }
    }
}

__global__ __launch_bounds__(512, 1) void mma_gemm_kernel(
    const __half* __restrict__ Ah, const __half* __restrict__ Bh,
    float* __restrict__ C, __half* __restrict__ Ch, int m_store, int do_relu)
{
    extern __shared__ char smraw[];
    uint32_t smem_base = smem_to_u32(smraw);
    int tid = threadIdx.x;
    int wid = tid >> 5;
    int lane = tid & 31;
    int wm = wid & 3;
    int wn = wid >> 2;
    int brow = blockIdx.x * 128;

    float acc[2][8][4];
    #pragma unroll
    for (int i = 0; i < 2; i++)
        #pragma unroll
        for (int j = 0; j < 8; j++)
            #pragma unroll
            for (int q = 0; q < 4; q++) acc[i][j][q] = 0.f;

    #pragma unroll
    for (int p = 0; p < NSTAGE - 1; p++) {
        load_chunk512(smem_base + (uint32_t)p * STAGE_BYTES, brow, p * KC, tid, Ah, Bh);
        asm volatile("cp.async.commit_group;" ::: "memory");
    }

    int a_row = wm * 32 + (lane & 15);
    int a_kc8 = (lane >> 4) << 3;
    int tg = lane >> 3;
    int b_nbase = wn * 64 + ((tg >> 1) << 3) + (lane & 7);
    int b_kc8 = (tg & 1) << 3;

    for (int i = 0; i < NCHUNK; i++) {
        uint32_t sb = smem_base + (uint32_t)(i & (NSTAGE - 1)) * STAGE_BYTES;
        asm volatile("cp.async.wait_group %0;" :: "n"(NSTAGE - 2) : "memory");
        __syncthreads();

        #pragma unroll
        for (int ks = 0; ks < 4; ks++) {
            int k = ks * 16;
            uint32_t ah[2][4], bh[4][4];
            #pragma unroll
            for (int g = 0; g < 2; g++) {
                uint32_t bo = (uint32_t)((a_row + g * 16) * 128 + (k + a_kc8) * 2);
                ldsm4(ah[g][0], ah[g][1], ah[g][2], ah[g][3], sb + ST_AH + SWZ128(bo));
            }
            #pragma unroll
            for (int j = 0; j < 4; j++) {
                uint32_t bo = (uint32_t)((b_nbase + j * 16) * 128 + (k + b_kc8) * 2);
                ldsm4(bh[j][0], bh[j][1], bh[j][2], bh[j][3], sb + ST_BH + SWZ128(bo));
            }
            #pragma unroll
            for (int mt = 0; mt < 2; mt++)
                #pragma unroll
                for (int nt = 0; nt < 8; nt++)
                    mma16816(acc[mt][nt], ah[mt], &bh[nt >> 1][(nt & 1) * 2]);
        }
        int j = i + NSTAGE - 1;
        if (j < NCHUNK) {
            uint32_t wb = smem_base + (uint32_t)(j & (NSTAGE - 1)) * STAGE_BYTES;
            load_chunk512(wb, brow, j * KC, tid, Ah, Bh);
        }
        asm volatile("cp.async.commit_group;" ::: "memory");
    }

    int col = wn * 64 + 2 * (lane & 3);
    #pragma unroll
    for (int mt = 0; mt < 2; mt++) {
        int r0 = brow + wm * 32 + mt * 16 + (lane >> 2);
        int r1 = r0 + 8;
        #pragma unroll
        for (int nt = 0; nt < 8; nt++) {
            float2 v0 = make_float2(acc[mt][nt][0], acc[mt][nt][1]);
            float2 v1 = make_float2(acc[mt][nt][2], acc[mt][nt][3]);
            if (do_relu) {
                v0.x = fmaxf(v0.x, 0.f); v0.y = fmaxf(v0.y, 0.f);
                v1.x = fmaxf(v1.x, 0.f); v1.y = fmaxf(v1.y, 0.f);
            }
            int c = col + nt * 8;
            if (Ch) {
                if (r0 < m_store)
                    *reinterpret_cast<uint32_t*>(&Ch[(size_t)r0 * HID + c]) = pack2h(v0.x, v0.y);
                if (r1 < m_store)
                    *reinterpret_cast<uint32_t*>(&Ch[(size_t)r1 * HID + c]) = pack2h(v1.x, v1.y);
            } else {
                if (r0 < m_store)
                    *reinterpret_cast<float2*>(&C[(size_t)r0 * HID + c]) = v0;
                if (r1 < m_store)
                    *reinterpret_cast<float2*>(&C[(size_t)r1 * HID + c]) = v1;
            }
        }
    }
}

// ---------------- launch ----------------
extern "C" void kernel_launch(void* const* d_in, const int* in_sizes, int n_in,
                              void* d_out, int out_size) {
    const int*   edge_index = nullptr;
    const int*   edge_type  = nullptr;
    const float* emb        = nullptr;
    const float* bases      = nullptr;
    const float* coeffs     = nullptr;
    const float* selfw      = nullptr;
    for (int i = 0; i < n_in; i++) {
        switch (in_sizes[i]) {
            case 2 * NEDGES:             edge_index = (const int*)d_in[i]; break;
            case NEDGES:                 edge_type  = (const int*)d_in[i]; break;
            case NNODES * HID:           emb        = (const float*)d_in[i]; break;
            case 2 * NBASES * HID * HID: bases      = (const float*)d_in[i]; break;
            case 2 * NREL * NBASES:      coeffs     = (const float*)d_in[i]; break;
            case 2 * HID * HID:          selfw      = (const float*)d_in[i]; break;
            default: break;
        }
    }
    const int* srcp = edge_index;
    const int* dstp = edge_index + NEDGES;
    float* outp = (float*)d_out;

    static cudaStream_t s1 = nullptr;
    static cudaEvent_t e0, e1, e2;
    if (!s1) {
        cudaStreamCreateWithFlags(&s1, cudaStreamNonBlocking);
        cudaEventCreateWithFlags(&e0, cudaEventDisableTiming);
        cudaEventCreateWithFlags(&e1, cudaEventDisableTiming);
        cudaEventCreateWithFlags(&e2, cudaEventDisableTiming);
    }

    int* deg8_p;
    __half *ah_p, *bh_p, *x1h_p;
    cudaGetSymbolAddress((void**)&deg8_p, g_deg8);
    cudaGetSymbolAddress((void**)&ah_p, g_Ah);
    cudaGetSymbolAddress((void**)&bh_p, g_Bh);
    cudaGetSymbolAddress((void**)&x1h_p, g_x1h);

    cudaFuncSetAttribute(mma_gemm_kernel, cudaFuncAttributeMaxDynamicSharedMemorySize, GEMM_SMEM);

    dim3 wsgrid(KTOT / 32, HID / 32);
    dim3 wsblk(32, 32);
    const int AGG_BLOCKS = (NNODES + 3) / 4;     // 12500
    int ggrid = 391;

    cudaEventRecord(e0, 0);

    // stream0: CSR build (rel-sorted) + agg0
    cudaMemsetAsync(deg8_p, 0, NNODES * NREL * sizeof(int), 0);
    hist_kernel<<<(NEDGES + 255) / 256, 256>>>(dstp, edge_type);
    scan_kernel<<<1, 1024>>>();
    scatter_kernel<<<(NEDGES + 255) / 256, 256>>>(srcp, dstp, edge_type);
    agg_kernel<false><<<AGG_BLOCKS, 256>>>(emb);

    // s1: weight prep for both layers (overlaps CSR + agg)
    cudaStreamWaitEvent(s1, e0, 0);
    wcat_kernel<<<KTOT, HID, 0, s1>>>(bases, coeffs, selfw, 0);
    wsplit_kernel<<<wsgrid, wsblk, 0, s1>>>(0);
    cudaEventRecord(e1, s1);
    wcat_kernel<<<KTOT, HID, 0, s1>>>(bases, coeffs, selfw, 1);
    wsplit_kernel<<<wsgrid, wsblk, 0, s1>>>(1);
    cudaEventRecord(e2, s1);

    // layer 0 GEMM -> fp16 x1
    cudaStreamWaitEvent(0, e1, 0);
    mma_gemm_kernel<<<ggrid, 512, GEMM_SMEM>>>(ah_p, bh_p, nullptr, x1h_p, NNODES, 1);

    // layer 1: gather from fp16 x1
    agg_kernel<true><<<AGG_BLOCKS, 256>>>(x1h_p);
    cudaStreamWaitEvent(0, e2, 0);
    mma_gemm_kernel<<<ggrid, 512, GEMM_SMEM>>>(ah_p, bh_p + (size_t)HID * KTOT,
                                               outp, nullptr, NNODES, 0);

    (void)out_size;
}

// round 15
// speedup vs baseline: 2.6346x; 1.2564x over previous
#include <cuda_runtime.h>
#include <cuda_fp16.h>
#include <cstdint>

// ---------------- problem constants ----------------
#define NNODES 50000
#define NEDGES 800000
#define NREL   8
#define HID    256
#define NBASES 30
#define KTOT   2304            // 8*256 relation cols + 256 self cols
#define MPAD   50176           // array padding; GEMM uses 391*128 = 50048 rows

// ---------------- device scratch (static, .bss zero-initialized) ----------------
__device__ int   g_deg8[NNODES * NREL];              // per-(node,rel) counts
__device__ int   g_total;                            // atomic edge-slot counter
__device__ float g_deginv[NNODES];
__device__ int   g_rowptr8[NNODES * NREL + 8];       // per-(node,rel) CSR offsets
__device__ int   g_cursor8[NNODES * NREL];
__device__ int   g_edges[NEDGES];                    // src only (grouped by node,rel)
__device__ __align__(256) __half g_Ah[(size_t)MPAD * KTOT];   // fp16 A; pad rows stay 0
__device__ float g_W[KTOT * HID];                    // W[k][o] fp32 (serial on s1)
__device__ __align__(256) __half g_Bh[2][HID * KTOT];  // per-layer W^T fp16: [o][k]
__device__ __align__(256) __half g_x1h[(size_t)MPAD * HID];   // fp16 layer-0 output

// ================= helpers =================
__device__ __forceinline__ uint32_t smem_to_u32(const void* p) {
    uint32_t a;
    asm("{ .reg .u64 t; cvta.to.shared.u64 t, %1; cvt.u32.u64 %0, t; }" : "=r"(a) : "l"(p));
    return a;
}
#define SWZ128(off) ((off) ^ (((off) >> 3) & 0x70))

__device__ __forceinline__ void cp16(uint32_t dst, const void* src) {
    asm volatile("cp.async.cg.shared.global [%0], [%1], 16;" :: "r"(dst), "l"(src));
}
__device__ __forceinline__ void ldsm4(uint32_t& r0, uint32_t& r1, uint32_t& r2, uint32_t& r3,
                                      uint32_t addr) {
    asm volatile("ldmatrix.sync.aligned.m8n8.x4.shared.b16 {%0,%1,%2,%3}, [%4];"
                 : "=r"(r0), "=r"(r1), "=r"(r2), "=r"(r3) : "r"(addr));
}
__device__ __forceinline__ void mma16816(float* c, const uint32_t* a, const uint32_t* b) {
    asm volatile("mma.sync.aligned.m16n8k16.row.col.f32.f16.f16.f32 "
                 "{%0,%1,%2,%3}, {%4,%5,%6,%7}, {%8,%9}, {%0,%1,%2,%3};"
                 : "+f"(c[0]), "+f"(c[1]), "+f"(c[2]), "+f"(c[3])
                 : "r"(a[0]), "r"(a[1]), "r"(a[2]), "r"(a[3]), "r"(b[0]), "r"(b[1]));
}

// ---------------- setup kernels ----------------
__global__ void hist_kernel(const int* __restrict__ dst, const int* __restrict__ rel) {
    int e = blockIdx.x * blockDim.x + threadIdx.x;
    if (e < NEDGES) atomicAdd(&g_deg8[dst[e] * NREL + rel[e]], 1);
}

// parallel CSR range assignment: order-free (atomic base per node)
__global__ void assign_kernel() {
    int i = blockIdx.x * blockDim.x + threadIdx.x;
    if (i >= NNODES) return;
    int4 p0 = *reinterpret_cast<const int4*>(&g_deg8[i * 8]);
    int4 p1 = *reinterpret_cast<const int4*>(&g_deg8[i * 8 + 4]);
    int d8[8] = { p0.x, p0.y, p0.z, p0.w, p1.x, p1.y, p1.z, p1.w };
    int v = d8[0] + d8[1] + d8[2] + d8[3] + d8[4] + d8[5] + d8[6] + d8[7];
    int base = atomicAdd(&g_total, v);
    int rp[8];
    int off = base;
    #pragma unroll
    for (int r = 0; r < 8; r++) { rp[r] = off; off += d8[r]; }
    *reinterpret_cast<int4*>(&g_rowptr8[i * 8])     = make_int4(rp[0], rp[1], rp[2], rp[3]);
    *reinterpret_cast<int4*>(&g_rowptr8[i * 8 + 4]) = make_int4(rp[4], rp[5], rp[6], rp[7]);
    // the 9th bound for node i is rp[7] + d8[7] = off; store into the slot that
    // agg reads as g_rowptr8[i*8+8] only if this node is the LAST... not valid with
    // arbitrary ordering, so agg uses a per-node end array instead: we store end in
    // g_cursor8 first, then scatter bumps cursors; agg reads ends from g_rowptr8? No:
    // simplest: keep a dedicated end bound in g_rowptr8[i*8+?]. We instead store the
    // per-node segment ends implicitly: agg recomputes from rp + d8 — but agg doesn't
    // know d8. Solution: g_rowptr8 stores the 8 STARTS, and agg's 9th bound comes from
    // g_end8[i] written here.
    *reinterpret_cast<int4*>(&g_cursor8[i * 8])     = make_int4(rp[0], rp[1], rp[2], rp[3]);
    *reinterpret_cast<int4*>(&g_cursor8[i * 8 + 4]) = make_int4(rp[4], rp[5], rp[6], rp[7]);
    g_deginv[i] = 1.0f / fmaxf((float)v, 1.0f);
    // store node-end bound (start of would-be rel 8) in the padding slot pattern:
    // reuse g_deg8 as end storage (its counts are no longer needed after this kernel)
    g_deg8[i * 8] = off;   // node end
}

__global__ void scatter_kernel(const int* __restrict__ src,
                               const int* __restrict__ dst,
                               const int* __restrict__ rel) {
    int e = blockIdx.x * blockDim.x + threadIdx.x;
    if (e < NEDGES) {
        int pos = atomicAdd(&g_cursor8[dst[e] * NREL + rel[e]], 1);
        g_edges[pos] = src[e];
    }
}

// ---------------- weight assembly: g_W[k][o] fp32 ----------------
__global__ void wcat_kernel(const float* __restrict__ bases,
                            const float* __restrict__ coeffs,
                            const float* __restrict__ selfw,
                            int l) {
    int k = blockIdx.x;
    int o = threadIdx.x;
    if (k < 2048) {
        int r = k >> 8;
        int i = k & 255;
        const float* cf = coeffs + (l * NREL + r) * NBASES;
        const float* bs = bases + ((size_t)l * NBASES) * HID * HID + i * HID + o;
        float s = 0.f;
        #pragma unroll 6
        for (int b = 0; b < NBASES; b++)
            s += cf[b] * bs[(size_t)b * HID * HID];
        g_W[k * HID + o] = s;
    } else {
        g_W[k * HID + o] = selfw[(size_t)l * HID * HID + (k - 2048) * HID + o];
    }
}

// transpose + fp16 convert into per-layer buffer (B single fp16)
__global__ void wsplit_kernel(int l) {
    __shared__ float t[32][33];
    int k0 = blockIdx.x * 32, o0 = blockIdx.y * 32;
    int tx = threadIdx.x, ty = threadIdx.y;
    t[ty][tx] = g_W[(k0 + ty) * HID + o0 + tx];
    __syncthreads();
    float v = t[tx][ty];
    g_Bh[l][(size_t)(o0 + ty) * KTOT + k0 + tx] = __float2half_rn(v);
}

// ---------------- vectorized aggregation (rel-grouped CSR) -> fp16 A rows --------
// 64 threads/node, one accumulator, 8 sequential segments. Templated on input type.
__device__ __forceinline__ uint32_t pack2h(float a, float b) {
    __half2 h = __halves2half2(__float2half_rn(a), __float2half_rn(b));
    return *reinterpret_cast<uint32_t*>(&h);
}
__device__ __forceinline__ void emit4(float4 v, __half* dst) {
    uint2 h;
    h.x = pack2h(v.x, v.y);
    h.y = pack2h(v.z, v.w);
    *reinterpret_cast<uint2*>(dst) = h;
}

template <bool HALF_IN>
__global__ __launch_bounds__(256) void agg_kernel(const void* __restrict__ xin) {
    int node = (blockIdx.x << 2) + (threadIdx.x >> 6);
    if (node >= NNODES) return;
    int c4 = threadIdx.x & 63;                 // 4-column group index
    const float4* x4 = reinterpret_cast<const float4*>(xin);
    const __half2* h2 = reinterpret_cast<const __half2*>(xin);
    float dinv = g_deginv[node];
    size_t base = (size_t)node * KTOT + (c4 << 2);

    int j0 = g_rowptr8[node * 8];
    #pragma unroll 1
    for (int r = 0; r < 8; r++) {
        int j1 = (r < 7) ? g_rowptr8[node * 8 + r + 1] : g_deg8[node * 8];  // end bound
        float4 a = make_float4(0.f, 0.f, 0.f, 0.f);
        #pragma unroll 2
        for (int j = j0; j < j1; j++) {
            int s = __ldg(&g_edges[j]);
            float4 v;
            if (HALF_IN) {
                uint2 raw = __ldg(reinterpret_cast<const uint2*>(&h2[(size_t)s * 128 + c4 * 2]));
                __half2 ha = *reinterpret_cast<__half2*>(&raw.x);
                __half2 hb = *reinterpret_cast<__half2*>(&raw.y);
                float2 fa = __half22float2(ha);
                float2 fb = __half22float2(hb);
                v = make_float4(fa.x, fa.y, fb.x, fb.y);
            } else {
                v = __ldg(&x4[(size_t)s * 64 + c4]);
            }
            a.x += v.x; a.y += v.y; a.z += v.z; a.w += v.w;
        }
        a.x *= dinv; a.y *= dinv; a.z *= dinv; a.w *= dinv;
        emit4(a, g_Ah + base + r * HID);
        j0 = j1;
    }
    // self column
    float4 self;
    if (HALF_IN) {
        uint2 raw = __ldg(reinterpret_cast<const uint2*>(&h2[(size_t)node * 128 + c4 * 2]));
        __half2 ha = *reinterpret_cast<__half2*>(&raw.x);
        __half2 hb = *reinterpret_cast<__half2*>(&raw.y);
        float2 fa = __half22float2(ha);
        float2 fb = __half22float2(hb);
        self = make_float4(fa.x, fa.y, fb.x, fb.y);
    } else {
        self = __ldg(&x4[(size_t)node * 64 + c4]);
    }
    emit4(self, g_Ah + base + 2048);
}

// ---------------- HMMA GEMM: C = A@Bh^T (1-pass fp16, 4-stage pipeline) ------
// Output: fp32 to C when Ch == nullptr, else fp16 to Ch (layer-0 path).
#define KC 64
#define NCHUNK (KTOT / KC)     // 36
#define NSTAGE 4
#define ST_AH 0
#define ST_BH (16 * 1024)
#define STAGE_BYTES (48 * 1024)
#define GEMM_SMEM (NSTAGE * STAGE_BYTES)

__device__ __forceinline__ void load_chunk512(uint32_t sb, int brow, int k0, int tid,
                                              const __half* Ah, const __half* Bh) {
    #pragma unroll
    for (int it = 0; it < 6; it++) {
        int u = tid + it * 512;
        if (u < 1024) {
            int r = u >> 3, c = u & 7;
            uint32_t so = SWZ128((uint32_t)(r * 128 + c * 16));
            cp16(sb + ST_AH + so, Ah + (size_t)(brow + r) * KTOT + k0 + c * 8);
        } else {
            int idx = u - 1024;
            int r = idx >> 3, c = idx & 7;
            uint32_t so = SWZ128((uint32_t)(r * 128 + c * 16));
            cp16(sb + ST_BH + so, Bh + (size_t)r * KTOT + k0 + c * 8);
        }
    }
}

__global__ __launch_bounds__(512, 1) void mma_gemm_kernel(
    const __half* __restrict__ Ah, const __half* __restrict__ Bh,
    float* __restrict__ C, __half* __restrict__ Ch, int m_store, int do_relu)
{
    extern __shared__ char smraw[];
    uint32_t smem_base = smem_to_u32(smraw);
    int tid = threadIdx.x;
    int wid = tid >> 5;
    int lane = tid & 31;
    int wm = wid & 3;
    int wn = wid >> 2;
    int brow = blockIdx.x * 128;

    float acc[2][8][4];
    #pragma unroll
    for (int i = 0; i < 2; i++)
        #pragma unroll
        for (int j = 0; j < 8; j++)
            #pragma unroll
            for (int q = 0; q < 4; q++) acc[i][j][q] = 0.f;

    #pragma unroll
    for (int p = 0; p < NSTAGE - 1; p++) {
        load_chunk512(smem_base + (uint32_t)p * STAGE_BYTES, brow, p * KC, tid, Ah, Bh);
        asm volatile("cp.async.commit_group;" ::: "memory");
    }

    int a_row = wm * 32 + (lane & 15);
    int a_kc8 = (lane >> 4) << 3;
    int tg = lane >> 3;
    int b_nbase = wn * 64 + ((tg >> 1) << 3) + (lane & 7);
    int b_kc8 = (tg & 1) << 3;

    for (int i = 0; i < NCHUNK; i++) {
        uint32_t sb = smem_base + (uint32_t)(i & (NSTAGE - 1)) * STAGE_BYTES;
        asm volatile("cp.async.wait_group %0;" :: "n"(NSTAGE - 2) : "memory");
        __syncthreads();

        #pragma unroll
        for (int ks = 0; ks < 4; ks++) {
            int k = ks * 16;
            uint32_t ah[2][4], bh[4][4];
            #pragma unroll
            for (int g = 0; g < 2; g++) {
                uint32_t bo = (uint32_t)((a_row + g * 16) * 128 + (k + a_kc8) * 2);
                ldsm4(ah[g][0], ah[g][1], ah[g][2], ah[g][3], sb + ST_AH + SWZ128(bo));
            }
            #pragma unroll
            for (int j = 0; j < 4; j++) {
                uint32_t bo = (uint32_t)((b_nbase + j * 16) * 128 + (k + b_kc8) * 2);
                ldsm4(bh[j][0], bh[j][1], bh[j][2], bh[j][3], sb + ST_BH + SWZ128(bo));
            }
            #pragma unroll
            for (int mt = 0; mt < 2; mt++)
                #pragma unroll
                for (int nt = 0; nt < 8; nt++)
                    mma16816(acc[mt][nt], ah[mt], &bh[nt >> 1][(nt & 1) * 2]);
        }
        int j = i + NSTAGE - 1;
        if (j < NCHUNK) {
            uint32_t wb = smem_base + (uint32_t)(j & (NSTAGE - 1)) * STAGE_BYTES;
            load_chunk512(wb, brow, j * KC, tid, Ah, Bh);
        }
        asm volatile("cp.async.commit_group;" ::: "memory");
    }

    int col = wn * 64 + 2 * (lane & 3);
    #pragma unroll
    for (int mt = 0; mt < 2; mt++) {
        int r0 = brow + wm * 32 + mt * 16 + (lane >> 2);
        int r1 = r0 + 8;
        #pragma unroll
        for (int nt = 0; nt < 8; nt++) {
            float2 v0 = make_float2(acc[mt][nt][0], acc[mt][nt][1]);
            float2 v1 = make_float2(acc[mt][nt][2], acc[mt][nt][3]);
            if (do_relu) {
                v0.x = fmaxf(v0.x, 0.f); v0.y = fmaxf(v0.y, 0.f);
                v1.x = fmaxf(v1.x, 0.f); v1.y = fmaxf(v1.y, 0.f);
            }
            int c = col + nt * 8;
            if (Ch) {
                if (r0 < m_store)
                    *reinterpret_cast<uint32_t*>(&Ch[(size_t)r0 * HID + c]) = pack2h(v0.x, v0.y);
                if (r1 < m_store)
                    *reinterpret_cast<uint32_t*>(&Ch[(size_t)r1 * HID + c]) = pack2h(v1.x, v1.y);
            } else {
                if (r0 < m_store)
                    *reinterpret_cast<float2*>(&C[(size_t)r0 * HID + c]) = v0;
                if (r1 < m_store)
                    *reinterpret_cast<float2*>(&C[(size_t)r1 * HID + c]) = v1;
            }
        }
    }
}

// ---------------- launch ----------------
extern "C" void kernel_launch(void* const* d_in, const int* in_sizes, int n_in,
                              void* d_out, int out_size) {
    const int*   edge_index = nullptr;
    const int*   edge_type  = nullptr;
    const float* emb        = nullptr;
    const float* bases      = nullptr;
    const float* coeffs     = nullptr;
    const float* selfw      = nullptr;
    for (int i = 0; i < n_in; i++) {
        switch (in_sizes[i]) {
            case 2 * NEDGES:             edge_index = (const int*)d_in[i]; break;
            case NEDGES:                 edge_type  = (const int*)d_in[i]; break;
            case NNODES * HID:           emb        = (const float*)d_in[i]; break;
            case 2 * NBASES * HID * HID: bases      = (const float*)d_in[i]; break;
            case 2 * NREL * NBASES:      coeffs     = (const float*)d_in[i]; break;
            case 2 * HID * HID:          selfw      = (const float*)d_in[i]; break;
            default: break;
        }
    }
    const int* srcp = edge_index;
    const int* dstp = edge_index + NEDGES;
    float* outp = (float*)d_out;

    static cudaStream_t s1 = nullptr;
    static cudaEvent_t e0, e1, e2;
    if (!s1) {
        cudaStreamCreateWithFlags(&s1, cudaStreamNonBlocking);
        cudaEventCreateWithFlags(&e0, cudaEventDisableTiming);
        cudaEventCreateWithFlags(&e1, cudaEventDisableTiming);
        cudaEventCreateWithFlags(&e2, cudaEventDisableTiming);
    }

    int *deg8_p, *total_p;
    __half *ah_p, *bh_p, *x1h_p;
    cudaGetSymbolAddress((void**)&deg8_p, g_deg8);
    cudaGetSymbolAddress((void**)&total_p, g_total);
    cudaGetSymbolAddress((void**)&ah_p, g_Ah);
    cudaGetSymbolAddress((void**)&bh_p, g_Bh);
    cudaGetSymbolAddress((void**)&x1h_p, g_x1h);

    cudaFuncSetAttribute(mma_gemm_kernel, cudaFuncAttributeMaxDynamicSharedMemorySize, GEMM_SMEM);

    dim3 wsgrid(KTOT / 32, HID / 32);
    dim3 wsblk(32, 32);
    const int AGG_BLOCKS = (NNODES + 3) / 4;     // 12500
    int ggrid = 391;

    cudaEventRecord(e0, 0);

    // stream0: CSR build (rel-grouped, order-free) + agg0
    cudaMemsetAsync(deg8_p, 0, NNODES * NREL * sizeof(int), 0);
    cudaMemsetAsync(total_p, 0, sizeof(int), 0);
    hist_kernel<<<(NEDGES + 255) / 256, 256>>>(dstp, edge_type);
    assign_kernel<<<(NNODES + 255) / 256, 256>>>();
    scatter_kernel<<<(NEDGES + 255) / 256, 256>>>(srcp, dstp, edge_type);
    agg_kernel<false><<<AGG_BLOCKS, 256>>>(emb);

    // s1: weight prep for both layers (overlaps CSR + agg)
    cudaStreamWaitEvent(s1, e0, 0);
    wcat_kernel<<<KTOT, HID, 0, s1>>>(bases, coeffs, selfw, 0);
    wsplit_kernel<<<wsgrid, wsblk, 0, s1>>>(0);
    cudaEventRecord(e1, s1);
    wcat_kernel<<<KTOT, HID, 0, s1>>>(bases, coeffs, selfw, 1);
    wsplit_kernel<<<wsgrid, wsblk, 0, s1>>>(1);
    cudaEventRecord(e2, s1);

    // layer 0 GEMM -> fp16 x1
    cudaStreamWaitEvent(0, e1, 0);
    mma_gemm_kernel<<<ggrid, 512, GEMM_SMEM>>>(ah_p, bh_p, nullptr, x1h_p, NNODES, 1);

    // layer 1: gather from fp16 x1
    agg_kernel<true><<<AGG_BLOCKS, 256>>>(x1h_p);
    cudaStreamWaitEvent(0, e2, 0);
    mma_gemm_kernel<<<ggrid, 512, GEMM_SMEM>>>(ah_p, bh_p + (size_t)HID * KTOT,
                                               outp, nullptr, NNODES, 0);

    (void)out_size;
}

// round 17
// speedup vs baseline: 2.6366x; 1.0008x over previous
#include <cuda_runtime.h>
#include <cuda_fp16.h>
#include <cstdint>

// ---------------- problem constants ----------------
#define NNODES 50000
#define NEDGES 800000
#define NREL   8
#define HID    256
#define NBASES 30
#define KTOT   2304            // 8*256 relation cols + 256 self cols
#define MPAD   50176           // array padding; GEMM uses 391*128 = 50048 rows

// ---------------- device scratch (static, .bss zero-initialized) ----------------
__device__ int   g_deg8[NNODES * NREL];              // per-(node,rel) counts / node-end after assign
__device__ int   g_total;                            // atomic edge-slot counter
__device__ float g_deginv[NNODES];
__device__ int   g_rowptr8[NNODES * NREL + 8];       // per-(node,rel) segment starts
__device__ int   g_cursor8[NNODES * NREL];
__device__ int   g_edges[NEDGES];                    // src only (grouped by node,rel)
__device__ __align__(256) __half g_Ah[(size_t)MPAD * KTOT];   // fp16 A; pad rows stay 0
__device__ float g_W[KTOT * HID];                    // W[k][o] fp32 (serial on s1)
__device__ __align__(256) __half g_Bh[2][HID * KTOT];  // per-layer W^T fp16: [o][k]
__device__ __align__(256) __half g_x1h[(size_t)MPAD * HID];   // fp16 layer-0 output

// ================= helpers =================
__device__ __forceinline__ uint32_t smem_to_u32(const void* p) {
    uint32_t a;
    asm("{ .reg .u64 t; cvta.to.shared.u64 t, %1; cvt.u32.u64 %0, t; }" : "=r"(a) : "l"(p));
    return a;
}
#define SWZ128(off) ((off) ^ (((off) >> 3) & 0x70))

__device__ __forceinline__ void cp16(uint32_t dst, const void* src) {
    asm volatile("cp.async.cg.shared.global [%0], [%1], 16;" :: "r"(dst), "l"(src));
}
__device__ __forceinline__ void ldsm4(uint32_t& r0, uint32_t& r1, uint32_t& r2, uint32_t& r3,
                                      uint32_t addr) {
    asm volatile("ldmatrix.sync.aligned.m8n8.x4.shared.b16 {%0,%1,%2,%3}, [%4];"
                 : "=r"(r0), "=r"(r1), "=r"(r2), "=r"(r3) : "r"(addr));
}
__device__ __forceinline__ void mma16816(float* c, const uint32_t* a, const uint32_t* b) {
    asm volatile("mma.sync.aligned.m16n8k16.row.col.f32.f16.f16.f32 "
                 "{%0,%1,%2,%3}, {%4,%5,%6,%7}, {%8,%9}, {%0,%1,%2,%3};"
                 : "+f"(c[0]), "+f"(c[1]), "+f"(c[2]), "+f"(c[3])
                 : "r"(a[0]), "r"(a[1]), "r"(a[2]), "r"(a[3]), "r"(b[0]), "r"(b[1]));
}

// ---------------- setup kernels ----------------
__global__ void hist_kernel(const int* __restrict__ dst, const int* __restrict__ rel) {
    int e = blockIdx.x * blockDim.x + threadIdx.x;
    if (e < NEDGES) atomicAdd(&g_deg8[dst[e] * NREL + rel[e]], 1);
}

// parallel CSR range assignment: order-free (atomic base per node)
__global__ void assign_kernel() {
    int i = blockIdx.x * blockDim.x + threadIdx.x;
    if (i >= NNODES) return;
    int4 p0 = *reinterpret_cast<const int4*>(&g_deg8[i * 8]);
    int4 p1 = *reinterpret_cast<const int4*>(&g_deg8[i * 8 + 4]);
    int d8[8] = { p0.x, p0.y, p0.z, p0.w, p1.x, p1.y, p1.z, p1.w };
    int v = d8[0] + d8[1] + d8[2] + d8[3] + d8[4] + d8[5] + d8[6] + d8[7];
    int base = atomicAdd(&g_total, v);
    int rp[8];
    int off = base;
    #pragma unroll
    for (int r = 0; r < 8; r++) { rp[r] = off; off += d8[r]; }
    *reinterpret_cast<int4*>(&g_rowptr8[i * 8])     = make_int4(rp[0], rp[1], rp[2], rp[3]);
    *reinterpret_cast<int4*>(&g_rowptr8[i * 8 + 4]) = make_int4(rp[4], rp[5], rp[6], rp[7]);
    *reinterpret_cast<int4*>(&g_cursor8[i * 8])     = make_int4(rp[0], rp[1], rp[2], rp[3]);
    *reinterpret_cast<int4*>(&g_cursor8[i * 8 + 4]) = make_int4(rp[4], rp[5], rp[6], rp[7]);
    g_deginv[i] = 1.0f / fmaxf((float)v, 1.0f);
    g_deg8[i * 8] = off;   // node end bound (counts no longer needed)
}

__global__ void scatter_kernel(const int* __restrict__ src,
                               const int* __restrict__ dst,
                               const int* __restrict__ rel) {
    int e = blockIdx.x * blockDim.x + threadIdx.x;
    if (e < NEDGES) {
        int pos = atomicAdd(&g_cursor8[dst[e] * NREL + rel[e]], 1);
        g_edges[pos] = src[e];
    }
}

// ---------------- weight assembly: g_W[k][o] fp32 ----------------
__global__ void wcat_kernel(const float* __restrict__ bases,
                            const float* __restrict__ coeffs,
                            const float* __restrict__ selfw,
                            int l) {
    int k = blockIdx.x;
    int o = threadIdx.x;
    if (k < 2048) {
        int r = k >> 8;
        int i = k & 255;
        const float* cf = coeffs + (l * NREL + r) * NBASES;
        const float* bs = bases + ((size_t)l * NBASES) * HID * HID + i * HID + o;
        float s = 0.f;
        #pragma unroll 6
        for (int b = 0; b < NBASES; b++)
            s += cf[b] * bs[(size_t)b * HID * HID];
        g_W[k * HID + o] = s;
    } else {
        g_W[k * HID + o] = selfw[(size_t)l * HID * HID + (k - 2048) * HID + o];
    }
}

// transpose + fp16 convert into per-layer buffer (B single fp16)
__global__ void wsplit_kernel(int l) {
    __shared__ float t[32][33];
    int k0 = blockIdx.x * 32, o0 = blockIdx.y * 32;
    int tx = threadIdx.x, ty = threadIdx.y;
    t[ty][tx] = g_W[(k0 + ty) * HID + o0 + tx];
    __syncthreads();
    float v = t[tx][ty];
    g_Bh[l][(size_t)(o0 + ty) * KTOT + k0 + tx] = __float2half_rn(v);
}

// ---------------- vectorized aggregation (rel-grouped CSR) -> fp16 A rows --------
// 64 threads/node, one accumulator, 8 sequential segments. Templated on input type.
// fp32 path uses packed f32x2 adds (Blackwell) — 2 ADDs per float4 instead of 4.
__device__ __forceinline__ uint32_t pack2h(float a, float b) {
    __half2 h = __halves2half2(__float2half_rn(a), __float2half_rn(b));
    return *reinterpret_cast<uint32_t*>(&h);
}
__device__ __forceinline__ void emit4(float4 v, __half* dst) {
    uint2 h;
    h.x = pack2h(v.x, v.y);
    h.y = pack2h(v.z, v.w);
    *reinterpret_cast<uint2*>(dst) = h;
}
__device__ __forceinline__ uint32_t cvt_f16x2(float lo, float hi) {
    uint32_t r;
    asm("cvt.rn.f16x2.f32 %0, %1, %2;" : "=r"(r) : "f"(hi), "f"(lo));
    return r;
}

template <bool HALF_IN>
__global__ __launch_bounds__(256) void agg_kernel(const void* __restrict__ xin) {
    int node = (blockIdx.x << 2) + (threadIdx.x >> 6);
    if (node >= NNODES) return;
    int c4 = threadIdx.x & 63;                 // 4-column group index
    const ulonglong2* x2 = reinterpret_cast<const ulonglong2*>(xin);
    const __half2* h2 = reinterpret_cast<const __half2*>(xin);
    float dinv = g_deginv[node];
    unsigned long long d2 =
        ((unsigned long long)__float_as_uint(dinv) << 32) | __float_as_uint(dinv);
    size_t base = (size_t)node * KTOT + (c4 << 2);

    int j0 = g_rowptr8[node * 8];
    #pragma unroll 1
    for (int r = 0; r < 8; r++) {
        int j1 = (r < 7) ? g_rowptr8[node * 8 + r + 1] : g_deg8[node * 8];  // end bound
        if (HALF_IN) {
            float4 a = make_float4(0.f, 0.f, 0.f, 0.f);
            #pragma unroll 2
            for (int j = j0; j < j1; j++) {
                int s = __ldg(&g_edges[j]);
                uint2 raw = __ldg(reinterpret_cast<const uint2*>(&h2[(size_t)s * 128 + c4 * 2]));
                __half2 ha = *reinterpret_cast<__half2*>(&raw.x);
                __half2 hb = *reinterpret_cast<__half2*>(&raw.y);
                float2 fa = __half22float2(ha);
                float2 fb = __half22float2(hb);
                a.x += fa.x; a.y += fa.y; a.z += fb.x; a.w += fb.y;
            }
            a.x *= dinv; a.y *= dinv; a.z *= dinv; a.w *= dinv;
            emit4(a, g_Ah + base + r * HID);
        } else {
            unsigned long long a01 = 0ull, a23 = 0ull;   // packed (0.f,0.f)
            #pragma unroll 2
            for (int j = j0; j < j1; j++) {
                int s = __ldg(&g_edges[j]);
                ulonglong2 v = __ldg(&x2[(size_t)s * 64 + c4]);
                asm("add.rn.f32x2 %0, %0, %1;" : "+l"(a01) : "l"(v.x));
                asm("add.rn.f32x2 %0, %0, %1;" : "+l"(a23) : "l"(v.y));
            }
            asm("mul.rn.f32x2 %0, %0, %1;" : "+l"(a01) : "l"(d2));
            asm("mul.rn.f32x2 %0, %0, %1;" : "+l"(a23) : "l"(d2));
            float f0 = __uint_as_float((uint32_t)a01);
            float f1 = __uint_as_float((uint32_t)(a01 >> 32));
            float f2 = __uint_as_float((uint32_t)a23);
            float f3 = __uint_as_float((uint32_t)(a23 >> 32));
            uint2 h;
            h.x = cvt_f16x2(f0, f1);
            h.y = cvt_f16x2(f2, f3);
            *reinterpret_cast<uint2*>(g_Ah + base + r * HID) = h;
        }
        j0 = j1;
    }
    // self column
    if (HALF_IN) {
        uint2 raw = __ldg(reinterpret_cast<const uint2*>(&h2[(size_t)node * 128 + c4 * 2]));
        *reinterpret_cast<uint2*>(g_Ah + base + 2048) = raw;   // already fp16, copy bits
    } else {
        ulonglong2 v = __ldg(&x2[(size_t)node * 64 + c4]);
        float f0 = __uint_as_float((uint32_t)v.x);
        float f1 = __uint_as_float((uint32_t)(v.x >> 32));
        float f2 = __uint_as_float((uint32_t)v.y);
        float f3 = __uint_as_float((uint32_t)(v.y >> 32));
        uint2 h;
        h.x = cvt_f16x2(f0, f1);
        h.y = cvt_f16x2(f2, f3);
        *reinterpret_cast<uint2*>(g_Ah + base + 2048) = h;
    }
}

// ---------------- HMMA GEMM: C = A@Bh^T (1-pass fp16, 4-stage pipeline) ------
// Output: fp32 to C when Ch == nullptr, else fp16 to Ch (layer-0 path).
#define KC 64
#define NCHUNK (KTOT / KC)     // 36
#define NSTAGE 4
#define ST_AH 0
#define ST_BH (16 * 1024)
#define STAGE_BYTES (48 * 1024)
#define GEMM_SMEM (NSTAGE * STAGE_BYTES)

__device__ __forceinline__ void load_chunk512(uint32_t sb, int brow, int k0, int tid,
                                              const __half* Ah, const __half* Bh) {
    #pragma unroll
    for (int it = 0; it < 6; it++) {
        int u = tid + it * 512;
        if (u < 1024) {
            int r = u >> 3, c = u & 7;
            uint32_t so = SWZ128((uint32_t)(r * 128 + c * 16));
            cp16(sb + ST_AH + so, Ah + (size_t)(brow + r) * KTOT + k0 + c * 8);
        } else {
            int idx = u - 1024;
            int r = idx >> 3, c = idx & 7;
            uint32_t so = SWZ128((uint32_t)(r * 128 + c * 16));
            cp16(sb + ST_BH + so, Bh + (size_t)r * KTOT + k0 + c * 8);
        }
    }
}

__global__ __launch_bounds__(512, 1) void mma_gemm_kernel(
    const __half* __restrict__ Ah, const __half* __restrict__ Bh,
    float* __restrict__ C, __half* __restrict__ Ch, int m_store, int do_relu)
{
    extern __shared__ char smraw[];
    uint32_t smem_base = smem_to_u32(smraw);
    int tid = threadIdx.x;
    int wid = tid >> 5;
    int lane = tid & 31;
    int wm = wid & 3;
    int wn = wid >> 2;
    int brow = blockIdx.x * 128;

    float acc[2][8][4];
    #pragma unroll
    for (int i = 0; i < 2; i++)
        #pragma unroll
        for (int j = 0; j < 8; j++)
            #pragma unroll
            for (int q = 0; q < 4; q++) acc[i][j][q] = 0.f;

    #pragma unroll
    for (int p = 0; p < NSTAGE - 1; p++) {
        load_chunk512(smem_base + (uint32_t)p * STAGE_BYTES, brow, p * KC, tid, Ah, Bh);
        asm volatile("cp.async.commit_group;" ::: "memory");
    }

    int a_row = wm * 32 + (lane & 15);
    int a_kc8 = (lane >> 4) << 3;
    int tg = lane >> 3;
    int b_nbase = wn * 64 + ((tg >> 1) << 3) + (lane & 7);
    int b_kc8 = (tg & 1) << 3;

    for (int i = 0; i < NCHUNK; i++) {
        uint32_t sb = smem_base + (uint32_t)(i & (NSTAGE - 1)) * STAGE_BYTES;
        asm volatile("cp.async.wait_group %0;" :: "n"(NSTAGE - 2) : "memory");
        __syncthreads();

        #pragma unroll
        for (int ks = 0; ks < 4; ks++) {
            int k = ks * 16;
            uint32_t ah[2][4], bh[4][4];
            #pragma unroll
            for (int g = 0; g < 2; g++) {
                uint32_t bo = (uint32_t)((a_row + g * 16) * 128 + (k + a_kc8) * 2);
                ldsm4(ah[g][0], ah[g][1], ah[g][2], ah[g][3], sb + ST_AH + SWZ128(bo));
            }
            #pragma unroll
            for (int j = 0; j < 4; j++) {
                uint32_t bo = (uint32_t)((b_nbase + j * 16) * 128 + (k + b_kc8) * 2);
                ldsm4(bh[j][0], bh[j][1], bh[j][2], bh[j][3], sb + ST_BH + SWZ128(bo));
            }
            #pragma unroll
            for (int mt = 0; mt < 2; mt++)
                #pragma unroll
                for (int nt = 0; nt < 8; nt++)
                    mma16816(acc[mt][nt], ah[mt], &bh[nt >> 1][(nt & 1) * 2]);
        }
        int j = i + NSTAGE - 1;
        if (j < NCHUNK) {
            uint32_t wb = smem_base + (uint32_t)(j & (NSTAGE - 1)) * STAGE_BYTES;
            load_chunk512(wb, brow, j * KC, tid, Ah, Bh);
        }
        asm volatile("cp.async.commit_group;" ::: "memory");
    }

    int col = wn * 64 + 2 * (lane & 3);
    #pragma unroll
    for (int mt = 0; mt < 2; mt++) {
        int r0 = brow + wm * 32 + mt * 16 + (lane >> 2);
        int r1 = r0 + 8;
        #pragma unroll
        for (int nt = 0; nt < 8; nt++) {
            float2 v0 = make_float2(acc[mt][nt][0], acc[mt][nt][1]);
            float2 v1 = make_float2(acc[mt][nt][2], acc[mt][nt][3]);
            if (do_relu) {
                v0.x = fmaxf(v0.x, 0.f); v0.y = fmaxf(v0.y, 0.f);
                v1.x = fmaxf(v1.x, 0.f); v1.y = fmaxf(v1.y, 0.f);
            }
            int c = col + nt * 8;
            if (Ch) {
                if (r0 < m_store)
                    *reinterpret_cast<uint32_t*>(&Ch[(size_t)r0 * HID + c]) = pack2h(v0.x, v0.y);
                if (r1 < m_store)
                    *reinterpret_cast<uint32_t*>(&Ch[(size_t)r1 * HID + c]) = pack2h(v1.x, v1.y);
            } else {
                if (r0 < m_store)
                    *reinterpret_cast<float2*>(&C[(size_t)r0 * HID + c]) = v0;
                if (r1 < m_store)
                    *reinterpret_cast<float2*>(&C[(size_t)r1 * HID + c]) = v1;
            }
        }
    }
}

// ---------------- launch ----------------
extern "C" void kernel_launch(void* const* d_in, const int* in_sizes, int n_in,
                              void* d_out, int out_size) {
    const int*   edge_index = nullptr;
    const int*   edge_type  = nullptr;
    const float* emb        = nullptr;
    const float* bases      = nullptr;
    const float* coeffs     = nullptr;
    const float* selfw      = nullptr;
    for (int i = 0; i < n_in; i++) {
        switch (in_sizes[i]) {
            case 2 * NEDGES:             edge_index = (const int*)d_in[i]; break;
            case NEDGES:                 edge_type  = (const int*)d_in[i]; break;
            case NNODES * HID:           emb        = (const float*)d_in[i]; break;
            case 2 * NBASES * HID * HID: bases      = (const float*)d_in[i]; break;
            case 2 * NREL * NBASES:      coeffs     = (const float*)d_in[i]; break;
            case 2 * HID * HID:          selfw      = (const float*)d_in[i]; break;
            default: break;
        }
    }
    const int* srcp = edge_index;
    const int* dstp = edge_index + NEDGES;
    float* outp = (float*)d_out;

    static cudaStream_t s1 = nullptr;
    static cudaEvent_t e0, e1, e2;
    if (!s1) {
        cudaStreamCreateWithFlags(&s1, cudaStreamNonBlocking);
        cudaEventCreateWithFlags(&e0, cudaEventDisableTiming);
        cudaEventCreateWithFlags(&e1, cudaEventDisableTiming);
        cudaEventCreateWithFlags(&e2, cudaEventDisableTiming);
    }

    int *deg8_p, *total_p;
    __half *ah_p, *bh_p, *x1h_p;
    cudaGetSymbolAddress((void**)&deg8_p, g_deg8);
    cudaGetSymbolAddress((void**)&total_p, g_total);
    cudaGetSymbolAddress((void**)&ah_p, g_Ah);
    cudaGetSymbolAddress((void**)&bh_p, g_Bh);
    cudaGetSymbolAddress((void**)&x1h_p, g_x1h);

    cudaFuncSetAttribute(mma_gemm_kernel, cudaFuncAttributeMaxDynamicSharedMemorySize, GEMM_SMEM);

    dim3 wsgrid(KTOT / 32, HID / 32);
    dim3 wsblk(32, 32);
    const int AGG_BLOCKS = (NNODES + 3) / 4;     // 12500
    int ggrid = 391;

    cudaEventRecord(e0, 0);

    // stream0: CSR build (rel-grouped, order-free) + agg0
    cudaMemsetAsync(deg8_p, 0, NNODES * NREL * sizeof(int), 0);
    cudaMemsetAsync(total_p, 0, sizeof(int), 0);
    hist_kernel<<<(NEDGES + 255) / 256, 256>>>(dstp, edge_type);
    assign_kernel<<<(NNODES + 255) / 256, 256>>>();
    scatter_kernel<<<(NEDGES + 255) / 256, 256>>>(srcp, dstp, edge_type);
    agg_kernel<false><<<AGG_BLOCKS, 256>>>(emb);

    // s1: weight prep for both layers (overlaps CSR + agg)
    cudaStreamWaitEvent(s1, e0, 0);
    wcat_kernel<<<KTOT, HID, 0, s1>>>(bases, coeffs, selfw, 0);
    wsplit_kernel<<<wsgrid, wsblk, 0, s1>>>(0);
    cudaEventRecord(e1, s1);
    wcat_kernel<<<KTOT, HID, 0, s1>>>(bases, coeffs, selfw, 1);
    wsplit_kernel<<<wsgrid, wsblk, 0, s1>>>(1);
    cudaEventRecord(e2, s1);

    // layer 0 GEMM -> fp16 x1
    cudaStreamWaitEvent(0, e1, 0);
    mma_gemm_kernel<<<ggrid, 512, GEMM_SMEM>>>(ah_p, bh_p, nullptr, x1h_p, NNODES, 1);

    // layer 1: gather from fp16 x1
    agg_kernel<true><<<AGG_BLOCKS, 256>>>(x1h_p);
    cudaStreamWaitEvent(0, e2, 0);
    mma_gemm_kernel<<<ggrid, 512, GEMM_SMEM>>>(ah_p, bh_p + (size_t)HID * KTOT,
                                               outp, nullptr, NNODES, 0);

    (void)out_size;
}